// round 13
// baseline (speedup 1.0000x reference)
#include <cuda_runtime.h>
#include <cuda_fp16.h>
#include <math.h>
#include <stdint.h>

#define DEPTH  6
#define DIM    512
#define QKVN   1536
#define HEADS  8
#define DH     64
#define NB     266
#define FFD    2048
#define OUTD   32
#define BATCH  4
#define SEQ    8192
#define MROWS  (BATCH*SEQ)   // 32768
#define BH     (BATCH*HEADS) // 32
#define MPAD   320
#define CTXW   80
#define BSTR   332           // fp32 stage stride (xfeat0)
#define HSTR   36            // uint stride for [*][64-half] tiles
#define QSTR   164           // uint stride for [*][320-half] tiles
#define EPSF   1e-4f
#define DN     0.3535533905932738f
#define RATIO  0.06131393394849658f
#define SPLITK 4
#define STG    3

// fp16 weight scratch offsets (halfs) — TRANSPOSED [N][K] layout, QKV concatenated
#define WQKVOFF 0
#define WOOFF   (3*DEPTH*DIM*DIM)
#define W1OFF   (4*DEPTH*DIM*DIM)
#define W2OFF   (4*DEPTH*DIM*DIM + DEPTH*DIM*FFD)
#define WRTOT   (4*DEPTH*DIM*DIM + 2*DEPTH*DIM*FFD)

// xfeat smem layout (uints): region0 23616 overlapped, aux after
#define AUXOFF  23616
#define XF_SMEM ((AUXOFF + 392)*4)

// ---------------- scratch ----------------
__device__ __align__(256) float  g_x[MROWS*DIM];
__device__ __align__(256) __half g_h[MROWS*DIM];
__device__ __align__(256) __half g_qkv[(size_t)MROWS*QKVN];
__device__ __align__(256) __half g_o[MROWS*DIM];
__device__ __align__(256) __half g_ff[(size_t)MROWS*FFD];
__device__ __align__(256) float  g_kpT[(size_t)BH*MPAD*SEQ];
__device__ __align__(256) float  g_ctx[BH*MPAD*CTXW];
__device__ __align__(256) __half g_ctxT[BH*CTXW*MPAD];
__device__ __align__(256) __half g_vT[(size_t)BH*DH*SEQ];
__device__ __align__(256) float  g_diag[BH*SEQ];
__device__ __align__(256) __half g_projH[DEPTH*MPAD*DH];
__device__ __align__(256) __half g_wh[WRTOT];
__device__ float g_kmax;

// ---------------- helpers ----------------
__device__ __forceinline__ void atomicMaxF(float* addr, float val) {
    int old = __float_as_int(*addr);
    while (__int_as_float(old) < val) {
        int assumed = old;
        old = atomicCAS((int*)addr, assumed, __float_as_int(val));
        if (old == assumed) break;
    }
}

__device__ __forceinline__ float fast_exp(float x) {
    float t = x * 1.4426950408889634f;
    t = fminf(fmaxf(t, -126.0f), 126.0f);
    float z = t + 12582912.0f;
    int n = __float_as_int(z) - 0x4B400000;
    float f = t - (z - 12582912.0f);
    float p = 1.33335581e-3f;
    p = fmaf(p, f, 9.61812911e-3f);
    p = fmaf(p, f, 5.55041087e-2f);
    p = fmaf(p, f, 2.40226507e-1f);
    p = fmaf(p, f, 6.93147181e-1f);
    p = fmaf(p, f, 1.0f);
    return p * __int_as_float((n + 127) << 23);
}

__device__ __forceinline__ float fast_rcp(float x) {
    float y = __int_as_float(0x7EF311C3 - __float_as_int(x));
    y = y * (2.0f - x * y);
    y = y * (2.0f - x * y);
    y = y * (2.0f - x * y);
    return y;
}

__device__ __forceinline__ float gelu_fast(float x) {
    float u = 0.7978845608028654f * (x + 0.044715f * x * x * x);
    u = fminf(fmaxf(u, -9.0f), 9.0f);
    float E = fast_exp(2.0f * u);
    float th = 1.0f - 2.0f * fast_rcp(E + 1.0f);
    return 0.5f * x * (1.0f + th);
}

__device__ __forceinline__ unsigned packh2(float a, float b) {
    __half2 h = __floats2half2_rn(a, b);
    return *(unsigned*)&h;
}

__device__ __forceinline__ void mma_f16(float (&d)[4], const unsigned (&a)[4], const unsigned (&b)[2]) {
    asm volatile(
        "mma.sync.aligned.m16n8k16.row.col.f32.f16.f16.f32 "
        "{%0,%1,%2,%3}, {%4,%5,%6,%7}, {%8,%9}, {%0,%1,%2,%3};\n"
        : "+f"(d[0]), "+f"(d[1]), "+f"(d[2]), "+f"(d[3])
        : "r"(a[0]), "r"(a[1]), "r"(a[2]), "r"(a[3]), "r"(b[0]), "r"(b[1]));
}

__device__ __forceinline__ void ldsm4(unsigned &d0, unsigned &d1, unsigned &d2, unsigned &d3,
                                      const unsigned* p) {
    unsigned a = (unsigned)__cvta_generic_to_shared(p);
    asm volatile("ldmatrix.sync.aligned.m8n8.x4.shared.b16 {%0,%1,%2,%3}, [%4];"
                 : "=r"(d0), "=r"(d1), "=r"(d2), "=r"(d3) : "r"(a));
}

__device__ __forceinline__ void cp16(void* s, const void* g) {
    unsigned saddr = (unsigned)__cvta_generic_to_shared(s);
    asm volatile("cp.async.cg.shared.global [%0], [%1], 16;\n" :: "r"(saddr), "l"(g));
}
__device__ __forceinline__ void cp_commit() { asm volatile("cp.async.commit_group;\n"); }
template<int N> __device__ __forceinline__ void cp_wait() {
    asm volatile("cp.async.wait_group %0;\n" :: "n"(N));
}

// ---------------- init / reset / prep ----------------
__global__ void copy_src_kernel(const float* __restrict__ src) {
    int i = blockIdx.x * blockDim.x + threadIdx.x;
    if (i < MROWS*DIM) g_x[i] = src[i];
}

__global__ void reset_kernel() {
    int i = blockIdx.x * blockDim.x + threadIdx.x;
    if (i < BH*MPAD*CTXW) g_ctx[i] = 0.f;
    if (i == 0) g_kmax = __int_as_float(0xff800000);
}

// transpose + fp16 weights: src [L][K][N] fp32 -> dst rows [n][K] half
__global__ void trh_kernel(const float* __restrict__ src, __half* __restrict__ dst,
                           int K, int N, size_t dstLayerStride) {
    __shared__ float t[32][33];
    const float* s = src + (size_t)blockIdx.z*K*N;
    __half* d = dst + (size_t)blockIdx.z*dstLayerStride;
    int gn = blockIdx.x*32, gk = blockIdx.y*32;
    int tx = threadIdx.x, ty = threadIdx.y;
    #pragma unroll
    for (int i = 0; i < 32; i += 8)
        t[ty+i][tx] = s[(size_t)(gk+ty+i)*N + gn+tx];
    __syncthreads();
    #pragma unroll
    for (int i = 0; i < 32; i += 8)
        d[(size_t)(gn+ty+i)*K + gk+tx] = __float2half_rn(t[tx][ty+i]);
}

// all layers' proj as half [L][MPAD][DH] (natural layout, zero-padded)
__global__ void projh_kernel(const float* __restrict__ proj) {
    int i = blockIdx.x * blockDim.x + threadIdx.x;
    if (i < DEPTH*MPAD*DH) {
        int L = i / (MPAD*DH);
        int r = i - L*(MPAD*DH);
        int f = r / DH, d = r - f*DH;
        float v = (f < NB) ? proj[((size_t)L*NB + f)*DH + d] : 0.f;
        g_projH[i] = __float2half_rn(v);
    }
}

// per-layer: v slice of qkv (half) -> g_vT[bh][d][n] half
__global__ void vt_kernel(const __half* __restrict__ qkv) {
    __shared__ __half t[32][33];
    int n0 = blockIdx.x*32, d0 = blockIdx.y*32, bh = blockIdx.z;
    int b = bh >> 3, hh = bh & 7;
    int tx = threadIdx.x, ty = threadIdx.y;
    const __half* vs = qkv + 2*DIM + hh*DH;
    #pragma unroll
    for (int i = 0; i < 32; i += 8)
        t[ty+i][tx] = vs[((size_t)(b*SEQ) + n0+ty+i)*QKVN + d0+tx];
    __syncthreads();
    #pragma unroll
    for (int i = 0; i < 32; i += 8)
        g_vT[((size_t)bh*DH + d0+ty+i)*SEQ + n0+tx] = t[tx][ty+i];
}

// per-layer: g_ctx [bh][m][80] fp32 -> g_ctxT [bh][col][m] half
__global__ void ctxt_kernel() {
    int i = blockIdx.x * blockDim.x + threadIdx.x;
    if (i < BH*CTXW*MPAD) {
        int bh = i / (CTXW*MPAD);
        int r = i - bh*(CTXW*MPAD);
        int col = r / MPAD, m = r - col*MPAD;
        g_ctxT[i] = __float2half_rn(g_ctx[((size_t)bh*MPAD + m)*CTXW + col]);
    }
}

// ---------------- LayerNorm (fp16 output) ----------------
__global__ void __launch_bounds__(128) ln_kernel(
    const float* __restrict__ x, const float* __restrict__ g,
    const float* __restrict__ b, __half* __restrict__ o)
{
    int row = blockIdx.x, tid = threadIdx.x, lane = tid & 31, w = tid >> 5;
    const float4 xv = ((const float4*)(x + (size_t)row*DIM))[tid];
    float s = xv.x + xv.y + xv.z + xv.w;
    float q = xv.x*xv.x + xv.y*xv.y + xv.z*xv.z + xv.w*xv.w;
    #pragma unroll
    for (int off = 16; off; off >>= 1) {
        s += __shfl_xor_sync(0xffffffffu, s, off);
        q += __shfl_xor_sync(0xffffffffu, q, off);
    }
    __shared__ float ss[4], sq[4];
    if (lane == 0) { ss[w] = s; sq[w] = q; }
    __syncthreads();
    float S = ss[0]+ss[1]+ss[2]+ss[3];
    float Q = sq[0]+sq[1]+sq[2]+sq[3];
    float mean = S * (1.0f/DIM);
    float var  = Q * (1.0f/DIM) - mean*mean;
    float inv  = rsqrtf(var + 1e-5f);
    float4 gv = ((const float4*)g)[tid];
    float4 bv = ((const float4*)b)[tid];
    __half2 h0 = __floats2half2_rn((xv.x - mean)*inv*gv.x + bv.x,
                                   (xv.y - mean)*inv*gv.y + bv.y);
    __half2 h1 = __floats2half2_rn((xv.z - mean)*inv*gv.z + bv.z,
                                   (xv.w - mean)*inv*gv.w + bv.w);
    __half2* op = (__half2*)(o + (size_t)row*DIM) + tid*2;
    op[0] = h0;
    op[1] = h1;
}

// ---------------- FP16 GEMM, cp.async 3-stage + ldmatrix (128 thr, warp 64x64, BK=32) ----
// 3 CTAs/SM (60KB smem, <=170 regs) for latency hiding.
template<int BIASF, int RESF, int GELUF, int OUTHALF>
__global__ void __launch_bounds__(128, 3) hgemm_kernel(
    const __half* __restrict__ A, const __half* __restrict__ WT,
    const float* __restrict__ bias, const float* __restrict__ res,
    void* __restrict__ Cv, int M, int N, int K)
{
    extern __shared__ unsigned smu[];
    const int TSZ = 128*20;
    unsigned* As = smu;
    unsigned* Bs = smu + STG*TSZ;

    const int tid = threadIdx.x, lane = tid & 31, warp = tid >> 5;
    const int wm = warp >> 1, wn = warp & 1;
    const int qg = lane >> 2, qt = lane & 3;
    const __half* Ab = A  + (size_t)(blockIdx.y*128)*K;
    const __half* Wb = WT + (size_t)(blockIdx.x*128)*K;

    const int cr = tid >> 2, cs = tid & 3;
    int so[4];
    const __half *ga[4], *gb[4];
    #pragma unroll
    for (int g = 0; g < 4; g++) {
        so[g] = (cr + 32*g)*20 + cs*4;
        ga[g] = Ab + (size_t)(cr + 32*g)*K + cs*8;
        gb[g] = Wb + (size_t)(cr + 32*g)*K + cs*8;
    }

    const int aidx = (wm*64 + (lane & 7) + ((lane >> 3) & 1)*8)*20 + ((lane >> 4) << 2);
    const int bidx = (wn*64 + (lane & 7) + ((lane >> 4) & 1)*8)*20 + (((lane >> 3) & 1) << 2);

    float acc[4][8][4];
    #pragma unroll
    for (int i = 0; i < 4; i++)
        #pragma unroll
        for (int j = 0; j < 8; j++)
            #pragma unroll
            for (int r = 0; r < 4; r++) acc[i][j][r] = 0.f;

    const int ntiles = K >> 5;

    #pragma unroll
    for (int s = 0; s < STG-1; s++) {
        unsigned* Ad = As + s*TSZ;
        unsigned* Bd = Bs + s*TSZ;
        const int ko = s*32;
        #pragma unroll
        for (int g = 0; g < 4; g++) {
            cp16(Ad + so[g], ga[g] + ko);
            cp16(Bd + so[g], gb[g] + ko);
        }
        cp_commit();
    }
    cp_wait<STG-2>();
    __syncthreads();

    int stg_c = 0;                      // consume stage
    int stg_p = STG-1;                  // produce stage (kt+STG-1) % STG, at kt=0

    #pragma unroll 1
    for (int kt = 0; kt < ntiles; kt++) {
        if (kt + STG-1 < ntiles) {
            unsigned* Ad = As + stg_p*TSZ;
            unsigned* Bd = Bs + stg_p*TSZ;
            const int ko = (kt + STG-1) * 32;
            #pragma unroll
            for (int g = 0; g < 4; g++) {
                cp16(Ad + so[g], ga[g] + ko);
                cp16(Bd + so[g], gb[g] + ko);
            }
        }
        cp_commit();

        const unsigned* At = As + stg_c*TSZ;
        const unsigned* Bt = Bs + stg_c*TSZ;
        #pragma unroll
        for (int kk = 0; kk < 2; kk++) {
            unsigned af[4][4], bf[8][2];
            #pragma unroll
            for (int i = 0; i < 4; i++)
                ldsm4(af[i][0], af[i][1], af[i][2], af[i][3],
                      At + aidx + i*320 + kk*8);
            #pragma unroll
            for (int j2 = 0; j2 < 4; j2++)
                ldsm4(bf[2*j2][0], bf[2*j2][1], bf[2*j2+1][0], bf[2*j2+1][1],
                      Bt + bidx + j2*320 + kk*8);
            #pragma unroll
            for (int i = 0; i < 4; i++)
                #pragma unroll
                for (int j = 0; j < 8; j++)
                    mma_f16(acc[i][j], af[i], bf[j]);
        }
        cp_wait<STG-2>();
        __syncthreads();
        stg_c = (stg_c == STG-1) ? 0 : stg_c + 1;
        stg_p = (stg_p == STG-1) ? 0 : stg_p + 1;
    }

    const int row0 = blockIdx.y*128 + wm*64;
    const int col0 = blockIdx.x*128 + wn*64;
    float*  Cf = (float*)Cv;
    __half* Ch = (__half*)Cv;
    #pragma unroll
    for (int i = 0; i < 4; i++) {
        #pragma unroll
        for (int j = 0; j < 8; j++) {
            int r = row0 + i*16 + qg;
            int c = col0 + j*8 + qt*2;
            float b0 = 0.f, b1 = 0.f;
            if (BIASF) { b0 = bias[c]; b1 = bias[c+1]; }
            float v0 = acc[i][j][0] + b0;
            float v1 = acc[i][j][1] + b1;
            float v2 = acc[i][j][2] + b0;
            float v3 = acc[i][j][3] + b1;
            if (GELUF) { v0 = gelu_fast(v0); v1 = gelu_fast(v1); v2 = gelu_fast(v2); v3 = gelu_fast(v3); }
            if (RESF) {
                const float2 r0v = *(const float2*)(res + (size_t)r*N + c);
                const float2 r1v = *(const float2*)(res + (size_t)(r+8)*N + c);
                v0 += r0v.x; v1 += r0v.y; v2 += r1v.x; v3 += r1v.y;
            }
            if (OUTHALF) {
                *(__half2*)(Ch + (size_t)r*N + c)     = __floats2half2_rn(v0, v1);
                *(__half2*)(Ch + (size_t)(r+8)*N + c) = __floats2half2_rn(v2, v3);
            } else {
                *(float2*)(Cf + (size_t)r*N + c)     = make_float2(v0, v1);
                *(float2*)(Cf + (size_t)(r+8)*N + c) = make_float2(v2, v3);
            }
        }
    }
}

// ---------------- feature-map kernels (FP16 MMA) ----------------
template<int ISQ>
__global__ void __launch_bounds__(256) xfeat_kernel(const __half* __restrict__ pH,
                                                   const __half* __restrict__ srcb)
{
    extern __shared__ unsigned smu[];
    unsigned* As = smu;
    unsigned* Ph = smu + 64*HSTR;
    float*    fstage = (float*)smu;
    unsigned* Qs = smu;
    unsigned* Ct = smu + 64*QSTR;
    float* s_aux  = (float*)(smu + AUXOFF);
    float* s_diag = s_aux;
    float* s_rmax = s_diag + 64;
    float* s_dnm  = s_rmax + 256;
    float* s_wm   = s_dnm + 64;

    const int tid = threadIdx.x, lane = tid & 31, warp = tid >> 5;
    const int qg = lane >> 2, qt = lane & 3;
    const int wm = warp >> 2, wn = warp & 3;
    const int bh = blockIdx.y, b = bh >> 3, hh = bh & 7;
    const int n0 = blockIdx.x * 64;
    const __half* src = srcb + ((size_t)b*SEQ + n0)*QKVN + hh*DH;
    const __half2 dn2 = __float2half2_rn(DN);

    #pragma unroll
    for (int i = tid; i < 64*8; i += 256) {
        int r = i >> 3, c4 = (i & 7) * 4;
        uint4 v = *(const uint4*)((const unsigned*)(src + (size_t)r*QKVN) + c4);
        __half2* hv = (__half2*)&v;
        hv[0] = __hmul2(hv[0], dn2);
        hv[1] = __hmul2(hv[1], dn2);
        hv[2] = __hmul2(hv[2], dn2);
        hv[3] = __hmul2(hv[3], dn2);
        *(uint4*)&As[r*HSTR + c4] = v;
    }
    #pragma unroll
    for (int i = tid; i < 2560; i += 256) {
        int r = i >> 3, c4 = (i & 7) * 4;
        uint4 v = *(const uint4*)((const unsigned*)pH + r*32 + c4);
        *(uint4*)&Ph[r*HSTR + c4] = v;
    }
    __syncthreads();

    if (tid < 64) {
        float s = 0.f;
        #pragma unroll 8
        for (int d = 0; d < 32; d++) {
            __half2 h = *(__half2*)&As[tid*HSTR + d];
            float2 f = __half22float2(h);
            s += f.x*f.x + f.y*f.y;
        }
        s = 0.5f * s;
        s_diag[tid] = s;
        if (!ISQ) g_diag[(size_t)bh*SEQ + n0 + tid] = s;
    }
    __syncthreads();

    float acc1[2][10][4];
    #pragma unroll
    for (int i = 0; i < 2; i++)
        #pragma unroll
        for (int j = 0; j < 10; j++)
            #pragma unroll
            for (int r = 0; r < 4; r++) acc1[i][j][r] = 0.f;

    #pragma unroll
    for (int s = 0; s < 4; s++) {
        const int base = s*8;
        unsigned af[2][4], bf[10][2];
        #pragma unroll
        for (int i = 0; i < 2; i++) {
            const unsigned* ap = As + (wm*32 + i*16 + qg)*HSTR + base + qt;
            af[i][0] = ap[0];
            af[i][1] = ap[8*HSTR];
            af[i][2] = ap[4];
            af[i][3] = ap[8*HSTR + 4];
        }
        #pragma unroll
        for (int j = 0; j < 10; j++) {
            const unsigned* bp = Ph + (wn*80 + j*8 + qg)*HSTR + base + qt;
            bf[j][0] = bp[0];
            bf[j][1] = bp[4];
        }
        #pragma unroll
        for (int i = 0; i < 2; i++)
            #pragma unroll
            for (int j = 0; j < 10; j++)
                mma_f16(acc1[i][j], af[i], bf[j]);
    }

    if (!ISQ) {
        float m = __int_as_float(0xff800000);
        #pragma unroll
        for (int i = 0; i < 2; i++)
            #pragma unroll
            for (int j = 0; j < 10; j++)
                #pragma unroll
                for (int r = 0; r < 4; r++) {
                    int col = wn*80 + j*8 + qt*2 + (r & 1);
                    if (col < NB) m = fmaxf(m, acc1[i][j][r]);
                }
        #pragma unroll
        for (int off = 16; off; off >>= 1) m = fmaxf(m, __shfl_xor_sync(0xffffffffu, m, off));
        if (lane == 0) s_wm[warp] = m;
        __syncthreads();
        if (tid == 0) {
            float mm = s_wm[0];
            #pragma unroll
            for (int i = 1; i < 8; i++) mm = fmaxf(mm, s_wm[i]);
            atomicMaxF(&g_kmax, mm);
        }
        #pragma unroll
        for (int i = 0; i < 2; i++)
            #pragma unroll
            for (int j = 0; j < 10; j++)
                #pragma unroll
                for (int r = 0; r < 4; r++) {
                    int row = wm*32 + i*16 + qg + 8*(r >> 1);
                    int col = wn*80 + j*8 + qt*2 + (r & 1);
                    fstage[row*BSTR + col] = (col < NB) ? acc1[i][j][r] : 0.f;
                }
        __syncthreads();
        #pragma unroll
        for (int i = tid; i < 64*80; i += 256) {
            int n = i & 63, f4 = (i >> 6) * 4;
            float4 v = *(const float4*)&fstage[n*BSTR + f4];
            float* dst = g_kpT + ((size_t)bh*MPAD + f4)*SEQ + n0 + n;
            dst[0]      = v.x;
            dst[SEQ]    = v.y;
            dst[2*SEQ]  = v.z;
            dst[3*SEQ]  = v.w;
        }
        return;
    }

    // rowmax
    #pragma unroll
    for (int i = 0; i < 2; i++) {
        #pragma unroll
        for (int h = 0; h < 2; h++) {
            float m = __int_as_float(0xff800000);
            #pragma unroll
            for (int j = 0; j < 10; j++) {
                #pragma unroll
                for (int rb = 0; rb < 2; rb++) {
                    int col = wn*80 + j*8 + qt*2 + rb;
                    if (col < NB) m = fmaxf(m, acc1[i][j][2*h + rb]);
                }
            }
            m = fmaxf(m, __shfl_xor_sync(0xffffffffu, m, 1));
            m = fmaxf(m, __shfl_xor_sync(0xffffffffu, m, 2));
            if (qt == 0) s_rmax[(wm*32 + i*16 + qg + 8*h)*4 + wn] = m;
        }
    }
    __syncthreads();

    float sub[2][2];
    #pragma unroll
    for (int i = 0; i < 2; i++)
        #pragma unroll
        for (int h = 0; h < 2; h++) {
            int row = wm*32 + i*16 + qg + 8*h;
            float m = fmaxf(fmaxf(s_rmax[row*4+0], s_rmax[row*4+1]),
                            fmaxf(s_rmax[row*4+2], s_rmax[row*4+3]));
            sub[i][h] = m + s_diag[row];
        }
    #pragma unroll
    for (int i = 0; i < 2; i++)
        #pragma unroll
        for (int j = 0; j < 10; j++)
            #pragma unroll
            for (int rp = 0; rp < 2; rp++) {
                int row = wm*32 + i*16 + qg + 8*rp;
                int col0 = wn*80 + j*8 + qt*2;
                float v0 = 0.f, v1 = 0.f;
                if (col0 < NB)
                    v0 = RATIO * (fast_exp(acc1[i][j][2*rp]   - sub[i][rp]) + EPSF);
                if (col0 + 1 < NB)
                    v1 = RATIO * (fast_exp(acc1[i][j][2*rp+1] - sub[i][rp]) + EPSF);
                Qs[row*QSTR + (col0 >> 1)] = packh2(v0, v1);
            }
    {
        const unsigned* cb = (const unsigned*)(g_ctxT + (size_t)bh*CTXW*MPAD);
        #pragma unroll
        for (int i = tid; i < 3200; i += 256) {
            int r = i / 40, c4 = (i % 40) * 4;
            uint4 v = *(const uint4*)(cb + r*160 + c4);
            *(uint4*)&Ct[r*QSTR + c4] = v;
        }
    }
    __syncthreads();

    const int wm2 = warp >> 1, wn2 = warp & 1;
    float acc2[5][4];
    #pragma unroll
    for (int j = 0; j < 5; j++)
        #pragma unroll
        for (int r = 0; r < 4; r++) acc2[j][r] = 0.f;

    #pragma unroll 5
    for (int s = 0; s < 20; s++) {
        const int base = s*8;
        unsigned af[4], bf[5][2];
        const unsigned* ap = Qs + (wm2*16 + qg)*QSTR + base + qt;
        af[0] = ap[0];
        af[1] = ap[8*QSTR];
        af[2] = ap[4];
        af[3] = ap[8*QSTR + 4];
        #pragma unroll
        for (int j = 0; j < 5; j++) {
            const unsigned* bp = Ct + (wn2*40 + j*8 + qg)*QSTR + base + qt;
            bf[j][0] = bp[0];
            bf[j][1] = bp[4];
        }
        #pragma unroll
        for (int j = 0; j < 5; j++)
            mma_f16(acc2[j], af, bf[j]);
    }

    #pragma unroll
    for (int j = 0; j < 5; j++)
        #pragma unroll
        for (int r = 0; r < 4; r++) {
            int col = wn2*40 + j*8 + qt*2 + (r & 1);
            if (col == 64) {
                int row = wm2*16 + qg + 8*(r >> 1);
                s_dnm[row] = acc2[j][r];
            }
        }
    __syncthreads();

    float invd0 = 1.0f / s_dnm[wm2*16 + qg];
    float invd1 = 1.0f / s_dnm[wm2*16 + qg + 8];
    __half* ob = g_o + ((size_t)b*SEQ + n0)*DIM + hh*DH;
    #pragma unroll
    for (int j = 0; j < 5; j++)
        #pragma unroll
        for (int r = 0; r < 4; r++) {
            int col = wn2*40 + j*8 + qt*2 + (r & 1);
            if (col < 64) {
                int row = wm2*16 + qg + 8*(r >> 1);
                ob[(size_t)row*DIM + col] = __float2half_rn(acc2[j][r] * ((r >> 1) ? invd1 : invd0));
            }
        }
}

// ---------------- ctx: read raw xp (fp32 kpT), fuse exp->half, fp16 MMA vs vT ----------------
__global__ void __launch_bounds__(256) ctx_kernel()
{
    __shared__ unsigned Xs[64*HSTR];
    __shared__ unsigned Bs[80*HSTR];
    const int tid = threadIdx.x, lane = tid & 31, warp = tid >> 5;
    const int qg = lane >> 2, qt = lane & 3;
    const int wm = warp >> 1, wn = warp & 1;
    const int f0 = blockIdx.x * 64, bh = blockIdx.y;
    const int nbase = blockIdx.z * (SEQ / SPLITK);
    const float km = g_kmax;

    if (tid >= 64 && tid < 80) {
        unsigned val = (tid == 64) ? 0x3C003C00u : 0u;
        #pragma unroll
        for (int c = 0; c < 32; c++) Bs[tid*HSTR + c] = val;
    }

    float acc[5][4];
    #pragma unroll
    for (int j = 0; j < 5; j++)
        #pragma unroll
        for (int r = 0; r < 4; r++) acc[j][r] = 0.f;

    for (int ch = 0; ch < SEQ/SPLITK; ch += 64) {
        __syncthreads();
        const int n0 = nbase + ch;
        #pragma unroll
        for (int i = tid; i < 64*16; i += 256) {
            int f = i >> 4, c = (i & 15);
            float4 v  = *(const float4*)(g_kpT + ((size_t)bh*MPAD + f0 + f)*SEQ + n0 + c*4);
            float4 dg = *(const float4*)(g_diag + (size_t)bh*SEQ + n0 + c*4);
            float e0 = RATIO * (fast_exp(v.x - dg.x - km) + EPSF);
            float e1 = RATIO * (fast_exp(v.y - dg.y - km) + EPSF);
            float e2 = RATIO * (fast_exp(v.z - dg.z - km) + EPSF);
            float e3 = RATIO * (fast_exp(v.w - dg.w - km) + EPSF);
            Xs[f*HSTR + 2*c]   = packh2(e0, e1);
            Xs[f*HSTR + 2*c+1] = packh2(e2, e3);
        }
        #pragma unroll
        for (int i = tid; i < 512; i += 256) {
            int d = i >> 3, c4 = (i & 7) * 4;
            const unsigned* vp = (const unsigned*)(g_vT + ((size_t)bh*DH + d)*SEQ + n0);
            *(uint4*)&Bs[d*HSTR + c4] = *(const uint4*)(vp + c4);
        }
        __syncthreads();
        #pragma unroll
        for (int s = 0; s < 4; s++) {
            const int base = s*8;
            unsigned af[4], bf[5][2];
            const unsigned* ap = Xs + (wm*16 + qg)*HSTR + base + qt;
            af[0] = ap[0];
            af[1] = ap[8*HSTR];
            af[2] = ap[4];
            af[3] = ap[8*HSTR + 4];
            #pragma unroll
            for (int j = 0; j < 5; j++) {
                const unsigned* bp = Bs + (wn*40 + j*8 + qg)*HSTR + base + qt;
                bf[j][0] = bp[0];
                bf[j][1] = bp[4];
            }
            #pragma unroll
            for (int j = 0; j < 5; j++)
                mma_f16(acc[j], af, bf[j]);
        }
    }

    float* cb = g_ctx + (size_t)bh*MPAD*CTXW;
    #pragma unroll
    for (int j = 0; j < 5; j++)
        #pragma unroll
        for (int r = 0; r < 4; r++) {
            int row = wm*16 + qg + 8*(r >> 1);
            int col = wn*40 + j*8 + qt*2 + (r & 1);
            if (col < 65)
                atomicAdd(&cb[(f0 + row)*CTXW + col], acc[j][r]);
        }
}

// ---------------- final fc ----------------
__global__ void __launch_bounds__(256) fc_kernel(
    const float* __restrict__ x, const float* __restrict__ w,
    const float* __restrict__ bias, float* __restrict__ out)
{
    __shared__ float xs[8*DIM];
    int tid = threadIdx.x;
    int m0 = blockIdx.x * 8;
    for (int i = tid; i < 8*DIM/4; i += 256)
        ((float4*)xs)[i] = ((const float4*)(x + (size_t)m0*DIM))[i];
    __syncthreads();
    int r = tid >> 5, c = tid & 31;
    float acc = 0.f;
    const float* xr = &xs[r*DIM];
    #pragma unroll 8
    for (int k = 0; k < DIM; k++) acc += xr[k] * w[k*OUTD + c];
    out[(size_t)(m0 + r)*OUTD + c] = acc + bias[c];
}

// ---------------- host launcher ----------------
extern "C" void kernel_launch(void* const* d_in, const int* in_sizes, int n_in,
                              void* d_out, int out_size)
{
    (void)in_sizes; (void)n_in; (void)out_size;
    const float* src  = (const float*)d_in[0];
    const float* proj = (const float*)d_in[1];
    const float* ln1g = (const float*)d_in[2];
    const float* ln1b = (const float*)d_in[3];
    const float* Wq   = (const float*)d_in[4];
    const float* Wk   = (const float*)d_in[5];
    const float* Wv   = (const float*)d_in[6];
    const float* Wo   = (const float*)d_in[7];
    const float* bo   = (const float*)d_in[8];
    const float* ln2g = (const float*)d_in[9];
    const float* ln2b = (const float*)d_in[10];
    const float* W1   = (const float*)d_in[11];
    const float* b1   = (const float*)d_in[12];
    const float* W2   = (const float*)d_in[13];
    const float* b2   = (const float*)d_in[14];
    const float* fcw  = (const float*)d_in[15];
    const float* fcb  = (const float*)d_in[16];
    float* out = (float*)d_out;

    float *xp;
    __half *hp, *qkvb, *ob, *ffb, *wh, *pH;
    cudaGetSymbolAddress((void**)&xp,   g_x);
    cudaGetSymbolAddress((void**)&hp,   g_h);
    cudaGetSymbolAddress((void**)&qkvb, g_qkv);
    cudaGetSymbolAddress((void**)&ob,   g_o);
    cudaGetSymbolAddress((void**)&ffb,  g_ff);
    cudaGetSymbolAddress((void**)&wh,   g_wh);
    cudaGetSymbolAddress((void**)&pH,   g_projH);

    const int gemm_smem = STG*2*(128*20)*4;   // 61440
    cudaFuncSetAttribute(hgemm_kernel<0,0,0,1>, cudaFuncAttributeMaxDynamicSharedMemorySize, gemm_smem);
    cudaFuncSetAttribute(hgemm_kernel<1,1,0,0>, cudaFuncAttributeMaxDynamicSharedMemorySize, gemm_smem);
    cudaFuncSetAttribute(hgemm_kernel<1,0,1,1>, cudaFuncAttributeMaxDynamicSharedMemorySize, gemm_smem);
    cudaFuncSetAttribute(xfeat_kernel<0>, cudaFuncAttributeMaxDynamicSharedMemorySize, XF_SMEM);
    cudaFuncSetAttribute(xfeat_kernel<1>, cudaFuncAttributeMaxDynamicSharedMemorySize, XF_SMEM);

    copy_src_kernel<<<(MROWS*DIM + 255)/256, 256>>>(src);

    dim3 tb(32, 8);
    trh_kernel<<<dim3(DIM/32, DIM/32, DEPTH), tb>>>(Wq, wh + WQKVOFF,                    DIM, DIM, (size_t)QKVN*DIM);
    trh_kernel<<<dim3(DIM/32, DIM/32, DEPTH), tb>>>(Wk, wh + WQKVOFF + (size_t)512*DIM,  DIM, DIM, (size_t)QKVN*DIM);
    trh_kernel<<<dim3(DIM/32, DIM/32, DEPTH), tb>>>(Wv, wh + WQKVOFF + (size_t)1024*DIM, DIM, DIM, (size_t)QKVN*DIM);
    trh_kernel<<<dim3(DIM/32, DIM/32, DEPTH), tb>>>(Wo, wh + WOOFF, DIM, DIM, (size_t)DIM*DIM);
    trh_kernel<<<dim3(FFD/32, DIM/32, DEPTH), tb>>>(W1, wh + W1OFF, DIM, FFD, (size_t)DIM*FFD);
    trh_kernel<<<dim3(DIM/32, FFD/32, DEPTH), tb>>>(W2, wh + W2OFF, FFD, DIM, (size_t)FFD*DIM);
    projh_kernel<<<(DEPTH*MPAD*DH + 255)/256, 256>>>(proj);

    dim3 gq(QKVN/128, MROWS/128);   // 12 x 256
    dim3 gg(DIM/128, MROWS/128);    // 4 x 256
    dim3 gf(FFD/128, MROWS/128);    // 16 x 256
    dim3 xg(SEQ/64, BH);            // 128 x 32

    for (int L = 0; L < DEPTH; L++) {
        const __half* pL = pH + (size_t)L*MPAD*DH;
        ln_kernel<<<MROWS, 128>>>(xp, ln1g + L*DIM, ln1b + L*DIM, hp);
        hgemm_kernel<0,0,0,1><<<gq, 128, gemm_smem>>>(hp, wh + WQKVOFF + (size_t)L*QKVN*DIM, 0, 0, qkvb, MROWS, QKVN, DIM);
        reset_kernel<<<(BH*MPAD*CTXW + 255)/256, 256>>>();
        vt_kernel<<<dim3(SEQ/32, DH/32, BH), tb>>>(qkvb);
        xfeat_kernel<0><<<xg, 256, XF_SMEM>>>(pL, qkvb + DIM);        // k cols [512,1024)
        ctx_kernel<<<dim3(MPAD/64, BH, SPLITK), 256>>>();
        ctxt_kernel<<<(BH*CTXW*MPAD + 255)/256, 256>>>();
        xfeat_kernel<1><<<xg, 256, XF_SMEM>>>(pL, qkvb);              // q cols [0,512)
        hgemm_kernel<1,1,0,0><<<gg, 128, gemm_smem>>>(ob, wh + WOOFF + (size_t)L*DIM*DIM, bo + L*DIM, xp, xp, MROWS, DIM, DIM);
        ln_kernel<<<MROWS, 128>>>(xp, ln2g + L*DIM, ln2b + L*DIM, hp);
        hgemm_kernel<1,0,1,1><<<gf, 128, gemm_smem>>>(hp, wh + W1OFF + (size_t)L*FFD*DIM, b1 + L*FFD, 0, ffb, MROWS, FFD, DIM);
        hgemm_kernel<1,1,0,0><<<gg, 128, gemm_smem>>>(ffb, wh + W2OFF + (size_t)L*DIM*FFD, b2 + L*DIM, xp, xp, MROWS, DIM, FFD);
    }
    fc_kernel<<<MROWS/8, 256>>>(xp, fcw, fcb, out);
}

// round 14
// speedup vs baseline: 1.0206x; 1.0206x over previous
#include <cuda_runtime.h>
#include <cuda_fp16.h>
#include <math.h>
#include <stdint.h>

#define DEPTH  6
#define DIM    512
#define QKVN   1536
#define HEADS  8
#define DH     64
#define NB     266
#define FFD    2048
#define OUTD   32
#define BATCH  4
#define SEQ    8192
#define MROWS  (BATCH*SEQ)   // 32768
#define BH     (BATCH*HEADS) // 32
#define MPAD   320
#define CTXW   80
#define BSTR   332           // fp32 stage stride (xfeat0)
#define HSTR   36            // uint stride for [*][64-half] tiles
#define QSTR   164           // uint stride for [*][320-half] tiles
#define EPSF   1e-4f
#define DN     0.3535533905932738f
#define RATIO  0.06131393394849658f
#define SPLITK 4
#define STG    4

// fp16 weight scratch offsets (halfs) — TRANSPOSED [N][K] layout, QKV concatenated
#define WQKVOFF 0
#define WOOFF   (3*DEPTH*DIM*DIM)
#define W1OFF   (4*DEPTH*DIM*DIM)
#define W2OFF   (4*DEPTH*DIM*DIM + DEPTH*DIM*FFD)
#define WRTOT   (4*DEPTH*DIM*DIM + 2*DEPTH*DIM*FFD)

// xfeat smem layout (uints): region0 23616 overlapped, aux after
#define AUXOFF  23616
#define XF_SMEM ((AUXOFF + 392)*4)

// ---------------- scratch ----------------
__device__ __align__(256) float  g_x[MROWS*DIM];
__device__ __align__(256) __half g_h[MROWS*DIM];
__device__ __align__(256) __half g_qkv[(size_t)MROWS*QKVN];
__device__ __align__(256) __half g_o[MROWS*DIM];
__device__ __align__(256) __half g_ff[(size_t)MROWS*FFD];
__device__ __align__(256) float  g_kpT[(size_t)BH*MPAD*SEQ];
__device__ __align__(256) float  g_ctx[BH*MPAD*CTXW];
__device__ __align__(256) __half g_ctxT[BH*CTXW*MPAD];
__device__ __align__(256) __half g_vT[(size_t)BH*DH*SEQ];
__device__ __align__(256) float  g_diag[BH*SEQ];
__device__ __align__(256) __half g_projH[DEPTH*MPAD*DH];
__device__ __align__(256) __half g_wh[WRTOT];
__device__ float g_kmax;

// ---------------- helpers ----------------
__device__ __forceinline__ void atomicMaxF(float* addr, float val) {
    int old = __float_as_int(*addr);
    while (__int_as_float(old) < val) {
        int assumed = old;
        old = atomicCAS((int*)addr, assumed, __float_as_int(val));
        if (old == assumed) break;
    }
}

__device__ __forceinline__ float fast_exp(float x) {
    float t = x * 1.4426950408889634f;
    t = fminf(fmaxf(t, -126.0f), 126.0f);
    float z = t + 12582912.0f;
    int n = __float_as_int(z) - 0x4B400000;
    float f = t - (z - 12582912.0f);
    float p = 1.33335581e-3f;
    p = fmaf(p, f, 9.61812911e-3f);
    p = fmaf(p, f, 5.55041087e-2f);
    p = fmaf(p, f, 2.40226507e-1f);
    p = fmaf(p, f, 6.93147181e-1f);
    p = fmaf(p, f, 1.0f);
    return p * __int_as_float((n + 127) << 23);
}

__device__ __forceinline__ float fast_rcp(float x) {
    float y = __int_as_float(0x7EF311C3 - __float_as_int(x));
    y = y * (2.0f - x * y);
    y = y * (2.0f - x * y);
    y = y * (2.0f - x * y);
    return y;
}

__device__ __forceinline__ float gelu_fast(float x) {
    float u = 0.7978845608028654f * (x + 0.044715f * x * x * x);
    u = fminf(fmaxf(u, -9.0f), 9.0f);
    float E = fast_exp(2.0f * u);
    float th = 1.0f - 2.0f * fast_rcp(E + 1.0f);
    return 0.5f * x * (1.0f + th);
}

__device__ __forceinline__ unsigned packh2(float a, float b) {
    __half2 h = __floats2half2_rn(a, b);
    return *(unsigned*)&h;
}

__device__ __forceinline__ void mma_f16(float (&d)[4], const unsigned (&a)[4], const unsigned (&b)[2]) {
    asm volatile(
        "mma.sync.aligned.m16n8k16.row.col.f32.f16.f16.f32 "
        "{%0,%1,%2,%3}, {%4,%5,%6,%7}, {%8,%9}, {%0,%1,%2,%3};\n"
        : "+f"(d[0]), "+f"(d[1]), "+f"(d[2]), "+f"(d[3])
        : "r"(a[0]), "r"(a[1]), "r"(a[2]), "r"(a[3]), "r"(b[0]), "r"(b[1]));
}

__device__ __forceinline__ void ldsm4(unsigned &d0, unsigned &d1, unsigned &d2, unsigned &d3,
                                      const unsigned* p) {
    unsigned a = (unsigned)__cvta_generic_to_shared(p);
    asm volatile("ldmatrix.sync.aligned.m8n8.x4.shared.b16 {%0,%1,%2,%3}, [%4];"
                 : "=r"(d0), "=r"(d1), "=r"(d2), "=r"(d3) : "r"(a));
}

__device__ __forceinline__ void cp16(void* s, const void* g) {
    unsigned saddr = (unsigned)__cvta_generic_to_shared(s);
    asm volatile("cp.async.cg.shared.global [%0], [%1], 16;\n" :: "r"(saddr), "l"(g));
}
__device__ __forceinline__ void cp_commit() { asm volatile("cp.async.commit_group;\n"); }
template<int N> __device__ __forceinline__ void cp_wait() {
    asm volatile("cp.async.wait_group %0;\n" :: "n"(N));
}

// ---------------- init / reset / prep ----------------
__global__ void copy_src_kernel(const float* __restrict__ src) {
    int i = blockIdx.x * blockDim.x + threadIdx.x;
    if (i < MROWS*DIM) g_x[i] = src[i];
}

__global__ void reset_kernel() {
    int i = blockIdx.x * blockDim.x + threadIdx.x;
    if (i < BH*MPAD*CTXW) g_ctx[i] = 0.f;
    if (i == 0) g_kmax = __int_as_float(0xff800000);
}

// transpose + fp16 weights: src [L][K][N] fp32 -> dst rows [n][K] half
__global__ void trh_kernel(const float* __restrict__ src, __half* __restrict__ dst,
                           int K, int N, size_t dstLayerStride) {
    __shared__ float t[32][33];
    const float* s = src + (size_t)blockIdx.z*K*N;
    __half* d = dst + (size_t)blockIdx.z*dstLayerStride;
    int gn = blockIdx.x*32, gk = blockIdx.y*32;
    int tx = threadIdx.x, ty = threadIdx.y;
    #pragma unroll
    for (int i = 0; i < 32; i += 8)
        t[ty+i][tx] = s[(size_t)(gk+ty+i)*N + gn+tx];
    __syncthreads();
    #pragma unroll
    for (int i = 0; i < 32; i += 8)
        d[(size_t)(gn+ty+i)*K + gk+tx] = __float2half_rn(t[tx][ty+i]);
}

// all layers' proj as half [L][MPAD][DH] (natural layout, zero-padded)
__global__ void projh_kernel(const float* __restrict__ proj) {
    int i = blockIdx.x * blockDim.x + threadIdx.x;
    if (i < DEPTH*MPAD*DH) {
        int L = i / (MPAD*DH);
        int r = i - L*(MPAD*DH);
        int f = r / DH, d = r - f*DH;
        float v = (f < NB) ? proj[((size_t)L*NB + f)*DH + d] : 0.f;
        g_projH[i] = __float2half_rn(v);
    }
}

// per-layer: g_ctx [bh][m][80] fp32 -> g_ctxT [bh][col][m] half
__global__ void ctxt_kernel() {
    int i = blockIdx.x * blockDim.x + threadIdx.x;
    if (i < BH*CTXW*MPAD) {
        int bh = i / (CTXW*MPAD);
        int r = i - bh*(CTXW*MPAD);
        int col = r / MPAD, m = r - col*MPAD;
        g_ctxT[i] = __float2half_rn(g_ctx[((size_t)bh*MPAD + m)*CTXW + col]);
    }
}

// ---------------- LayerNorm (fp16 output) ----------------
__global__ void __launch_bounds__(128) ln_kernel(
    const float* __restrict__ x, const float* __restrict__ g,
    const float* __restrict__ b, __half* __restrict__ o)
{
    int row = blockIdx.x, tid = threadIdx.x, lane = tid & 31, w = tid >> 5;
    const float4 xv = ((const float4*)(x + (size_t)row*DIM))[tid];
    float s = xv.x + xv.y + xv.z + xv.w;
    float q = xv.x*xv.x + xv.y*xv.y + xv.z*xv.z + xv.w*xv.w;
    #pragma unroll
    for (int off = 16; off; off >>= 1) {
        s += __shfl_xor_sync(0xffffffffu, s, off);
        q += __shfl_xor_sync(0xffffffffu, q, off);
    }
    __shared__ float ss[4], sq[4];
    if (lane == 0) { ss[w] = s; sq[w] = q; }
    __syncthreads();
    float S = ss[0]+ss[1]+ss[2]+ss[3];
    float Q = sq[0]+sq[1]+sq[2]+sq[3];
    float mean = S * (1.0f/DIM);
    float var  = Q * (1.0f/DIM) - mean*mean;
    float inv  = rsqrtf(var + 1e-5f);
    float4 gv = ((const float4*)g)[tid];
    float4 bv = ((const float4*)b)[tid];
    __half2 h0 = __floats2half2_rn((xv.x - mean)*inv*gv.x + bv.x,
                                   (xv.y - mean)*inv*gv.y + bv.y);
    __half2 h1 = __floats2half2_rn((xv.z - mean)*inv*gv.z + bv.z,
                                   (xv.w - mean)*inv*gv.w + bv.w);
    __half2* op = (__half2*)(o + (size_t)row*DIM) + tid*2;
    op[0] = h0;
    op[1] = h1;
}

// ---------------- FP16 GEMM, cp.async 4-stage + ldmatrix (128 thr, warp 64x64, BK=32) ----
// QKVF: v-region columns (col0>=1024) are written transposed to g_vT instead of C.
template<int BIASF, int RESF, int GELUF, int OUTHALF, int QKVF>
__global__ void __launch_bounds__(128, 2) hgemm_kernel(
    const __half* __restrict__ A, const __half* __restrict__ WT,
    const float* __restrict__ bias, const float* __restrict__ res,
    void* __restrict__ Cv, int M, int N, int K)
{
    extern __shared__ unsigned smu[];
    const int TSZ = 128*20;
    unsigned* As = smu;
    unsigned* Bs = smu + STG*TSZ;

    const int tid = threadIdx.x, lane = tid & 31, warp = tid >> 5;
    const int wm = warp >> 1, wn = warp & 1;
    const int qg = lane >> 2, qt = lane & 3;
    const __half* Ab = A  + (size_t)(blockIdx.y*128)*K;
    const __half* Wb = WT + (size_t)(blockIdx.x*128)*K;

    const int cr = tid >> 2, cs = tid & 3;
    int so[4];
    const __half *ga[4], *gb[4];
    #pragma unroll
    for (int g = 0; g < 4; g++) {
        so[g] = (cr + 32*g)*20 + cs*4;
        ga[g] = Ab + (size_t)(cr + 32*g)*K + cs*8;
        gb[g] = Wb + (size_t)(cr + 32*g)*K + cs*8;
    }

    const int aidx = (wm*64 + (lane & 7) + ((lane >> 3) & 1)*8)*20 + ((lane >> 4) << 2);
    const int bidx = (wn*64 + (lane & 7) + ((lane >> 4) & 1)*8)*20 + (((lane >> 3) & 1) << 2);

    float acc[4][8][4];
    #pragma unroll
    for (int i = 0; i < 4; i++)
        #pragma unroll
        for (int j = 0; j < 8; j++)
            #pragma unroll
            for (int r = 0; r < 4; r++) acc[i][j][r] = 0.f;

    const int ntiles = K >> 5;

    #pragma unroll
    for (int s = 0; s < STG-1; s++) {
        unsigned* Ad = As + s*TSZ;
        unsigned* Bd = Bs + s*TSZ;
        const int ko = s*32;
        #pragma unroll
        for (int g = 0; g < 4; g++) {
            cp16(Ad + so[g], ga[g] + ko);
            cp16(Bd + so[g], gb[g] + ko);
        }
        cp_commit();
    }
    cp_wait<STG-2>();
    __syncthreads();

    #pragma unroll 1
    for (int kt = 0; kt < ntiles; kt++) {
        const int stg = kt & (STG-1);
        if (kt + STG-1 < ntiles) {
            const int ns = (kt + STG-1) & (STG-1);
            unsigned* Ad = As + ns*TSZ;
            unsigned* Bd = Bs + ns*TSZ;
            const int ko = (kt + STG-1) * 32;
            #pragma unroll
            for (int g = 0; g < 4; g++) {
                cp16(Ad + so[g], ga[g] + ko);
                cp16(Bd + so[g], gb[g] + ko);
            }
        }
        cp_commit();

        const unsigned* At = As + stg*TSZ;
        const unsigned* Bt = Bs + stg*TSZ;
        #pragma unroll
        for (int kk = 0; kk < 2; kk++) {
            unsigned af[4][4], bf[8][2];
            #pragma unroll
            for (int i = 0; i < 4; i++)
                ldsm4(af[i][0], af[i][1], af[i][2], af[i][3],
                      At + aidx + i*320 + kk*8);
            #pragma unroll
            for (int j2 = 0; j2 < 4; j2++)
                ldsm4(bf[2*j2][0], bf[2*j2][1], bf[2*j2+1][0], bf[2*j2+1][1],
                      Bt + bidx + j2*320 + kk*8);
            #pragma unroll
            for (int i = 0; i < 4; i++)
                #pragma unroll
                for (int j = 0; j < 8; j++)
                    mma_f16(acc[i][j], af[i], bf[j]);
        }
        cp_wait<STG-2>();
        __syncthreads();
    }

    const int row0 = blockIdx.y*128 + wm*64;
    const int col0 = blockIdx.x*128 + wn*64;
    float*  Cf = (float*)Cv;
    __half* Ch = (__half*)Cv;

    if (QKVF && col0 >= 1024) {
        // v region: write transposed into g_vT[bh][d][n]
        #pragma unroll
        for (int i = 0; i < 4; i++) {
            #pragma unroll
            for (int j = 0; j < 8; j++) {
                int r = row0 + i*16 + qg;
                int c = col0 + j*8 + qt*2;
                int b = r >> 13, n = r & (SEQ-1);
                int bh = b*8 + ((c - 1024) >> 6);
                int d  = (c - 1024) & 63;
                __half* vp = g_vT + ((size_t)bh*DH + d)*SEQ;
                vp[n]            = __float2half_rn(acc[i][j][0]);
                vp[SEQ + n]      = __float2half_rn(acc[i][j][1]);
                vp[n + 8]        = __float2half_rn(acc[i][j][2]);
                vp[SEQ + n + 8]  = __float2half_rn(acc[i][j][3]);
            }
        }
        return;
    }

    #pragma unroll
    for (int i = 0; i < 4; i++) {
        #pragma unroll
        for (int j = 0; j < 8; j++) {
            int r = row0 + i*16 + qg;
            int c = col0 + j*8 + qt*2;
            float b0 = 0.f, b1 = 0.f;
            if (BIASF) { b0 = bias[c]; b1 = bias[c+1]; }
            float v0 = acc[i][j][0] + b0;
            float v1 = acc[i][j][1] + b1;
            float v2 = acc[i][j][2] + b0;
            float v3 = acc[i][j][3] + b1;
            if (GELUF) { v0 = gelu_fast(v0); v1 = gelu_fast(v1); v2 = gelu_fast(v2); v3 = gelu_fast(v3); }
            if (RESF) {
                const float2 r0v = *(const float2*)(res + (size_t)r*N + c);
                const float2 r1v = *(const float2*)(res + (size_t)(r+8)*N + c);
                v0 += r0v.x; v1 += r0v.y; v2 += r1v.x; v3 += r1v.y;
            }
            if (OUTHALF) {
                *(__half2*)(Ch + (size_t)r*N + c)     = __floats2half2_rn(v0, v1);
                *(__half2*)(Ch + (size_t)(r+8)*N + c) = __floats2half2_rn(v2, v3);
            } else {
                *(float2*)(Cf + (size_t)r*N + c)     = make_float2(v0, v1);
                *(float2*)(Cf + (size_t)(r+8)*N + c) = make_float2(v2, v3);
            }
        }
    }
}

// ---------------- feature-map kernels (FP16 MMA) ----------------
template<int ISQ>
__global__ void __launch_bounds__(256) xfeat_kernel(const __half* __restrict__ pH,
                                                   const __half* __restrict__ srcb)
{
    extern __shared__ unsigned smu[];
    unsigned* As = smu;
    unsigned* Ph = smu + 64*HSTR;
    float*    fstage = (float*)smu;
    unsigned* Qs = smu;
    unsigned* Ct = smu + 64*QSTR;
    float* s_aux  = (float*)(smu + AUXOFF);
    float* s_diag = s_aux;
    float* s_rmax = s_diag + 64;
    float* s_dnm  = s_rmax + 256;
    float* s_wm   = s_dnm + 64;

    const int tid = threadIdx.x, lane = tid & 31, warp = tid >> 5;
    const int qg = lane >> 2, qt = lane & 3;
    const int wm = warp >> 2, wn = warp & 3;
    const int bh = blockIdx.y, b = bh >> 3, hh = bh & 7;
    const int n0 = blockIdx.x * 64;
    const __half* src = srcb + ((size_t)b*SEQ + n0)*QKVN + hh*DH;
    const __half2 dn2 = __float2half2_rn(DN);

    #pragma unroll
    for (int i = tid; i < 64*8; i += 256) {
        int r = i >> 3, c4 = (i & 7) * 4;
        uint4 v = *(const uint4*)((const unsigned*)(src + (size_t)r*QKVN) + c4);
        __half2* hv = (__half2*)&v;
        hv[0] = __hmul2(hv[0], dn2);
        hv[1] = __hmul2(hv[1], dn2);
        hv[2] = __hmul2(hv[2], dn2);
        hv[3] = __hmul2(hv[3], dn2);
        *(uint4*)&As[r*HSTR + c4] = v;
    }
    #pragma unroll
    for (int i = tid; i < 2560; i += 256) {
        int r = i >> 3, c4 = (i & 7) * 4;
        uint4 v = *(const uint4*)((const unsigned*)pH + r*32 + c4);
        *(uint4*)&Ph[r*HSTR + c4] = v;
    }
    __syncthreads();

    if (tid < 64) {
        float s = 0.f;
        #pragma unroll 8
        for (int d = 0; d < 32; d++) {
            __half2 h = *(__half2*)&As[tid*HSTR + d];
            float2 f = __half22float2(h);
            s += f.x*f.x + f.y*f.y;
        }
        s = 0.5f * s;
        s_diag[tid] = s;
        if (!ISQ) g_diag[(size_t)bh*SEQ + n0 + tid] = s;
    }
    __syncthreads();

    float acc1[2][10][4];
    #pragma unroll
    for (int i = 0; i < 2; i++)
        #pragma unroll
        for (int j = 0; j < 10; j++)
            #pragma unroll
            for (int r = 0; r < 4; r++) acc1[i][j][r] = 0.f;

    #pragma unroll
    for (int s = 0; s < 4; s++) {
        const int base = s*8;
        unsigned af[2][4], bf[10][2];
        #pragma unroll
        for (int i = 0; i < 2; i++) {
            const unsigned* ap = As + (wm*32 + i*16 + qg)*HSTR + base + qt;
            af[i][0] = ap[0];
            af[i][1] = ap[8*HSTR];
            af[i][2] = ap[4];
            af[i][3] = ap[8*HSTR + 4];
        }
        #pragma unroll
        for (int j = 0; j < 10; j++) {
            const unsigned* bp = Ph + (wn*80 + j*8 + qg)*HSTR + base + qt;
            bf[j][0] = bp[0];
            bf[j][1] = bp[4];
        }
        #pragma unroll
        for (int i = 0; i < 2; i++)
            #pragma unroll
            for (int j = 0; j < 10; j++)
                mma_f16(acc1[i][j], af[i], bf[j]);
    }

    if (!ISQ) {
        float m = __int_as_float(0xff800000);
        #pragma unroll
        for (int i = 0; i < 2; i++)
            #pragma unroll
            for (int j = 0; j < 10; j++)
                #pragma unroll
                for (int r = 0; r < 4; r++) {
                    int col = wn*80 + j*8 + qt*2 + (r & 1);
                    if (col < NB) m = fmaxf(m, acc1[i][j][r]);
                }
        #pragma unroll
        for (int off = 16; off; off >>= 1) m = fmaxf(m, __shfl_xor_sync(0xffffffffu, m, off));
        if (lane == 0) s_wm[warp] = m;
        __syncthreads();
        if (tid == 0) {
            float mm = s_wm[0];
            #pragma unroll
            for (int i = 1; i < 8; i++) mm = fmaxf(mm, s_wm[i]);
            atomicMaxF(&g_kmax, mm);
        }
        #pragma unroll
        for (int i = 0; i < 2; i++)
            #pragma unroll
            for (int j = 0; j < 10; j++)
                #pragma unroll
                for (int r = 0; r < 4; r++) {
                    int row = wm*32 + i*16 + qg + 8*(r >> 1);
                    int col = wn*80 + j*8 + qt*2 + (r & 1);
                    fstage[row*BSTR + col] = (col < NB) ? acc1[i][j][r] : 0.f;
                }
        __syncthreads();
        #pragma unroll
        for (int i = tid; i < 64*80; i += 256) {
            int n = i & 63, f4 = (i >> 6) * 4;
            float4 v = *(const float4*)&fstage[n*BSTR + f4];
            float* dst = g_kpT + ((size_t)bh*MPAD + f4)*SEQ + n0 + n;
            dst[0]      = v.x;
            dst[SEQ]    = v.y;
            dst[2*SEQ]  = v.z;
            dst[3*SEQ]  = v.w;
        }
        return;
    }

    // rowmax
    #pragma unroll
    for (int i = 0; i < 2; i++) {
        #pragma unroll
        for (int h = 0; h < 2; h++) {
            float m = __int_as_float(0xff800000);
            #pragma unroll
            for (int j = 0; j < 10; j++) {
                #pragma unroll
                for (int rb = 0; rb < 2; rb++) {
                    int col = wn*80 + j*8 + qt*2 + rb;
                    if (col < NB) m = fmaxf(m, acc1[i][j][2*h + rb]);
                }
            }
            m = fmaxf(m, __shfl_xor_sync(0xffffffffu, m, 1));
            m = fmaxf(m, __shfl_xor_sync(0xffffffffu, m, 2));
            if (qt == 0) s_rmax[(wm*32 + i*16 + qg + 8*h)*4 + wn] = m;
        }
    }
    __syncthreads();

    float sub[2][2];
    #pragma unroll
    for (int i = 0; i < 2; i++)
        #pragma unroll
        for (int h = 0; h < 2; h++) {
            int row = wm*32 + i*16 + qg + 8*h;
            float m = fmaxf(fmaxf(s_rmax[row*4+0], s_rmax[row*4+1]),
                            fmaxf(s_rmax[row*4+2], s_rmax[row*4+3]));
            sub[i][h] = m + s_diag[row];
        }
    #pragma unroll
    for (int i = 0; i < 2; i++)
        #pragma unroll
        for (int j = 0; j < 10; j++)
            #pragma unroll
            for (int rp = 0; rp < 2; rp++) {
                int row = wm*32 + i*16 + qg + 8*rp;
                int col0 = wn*80 + j*8 + qt*2;
                float v0 = 0.f, v1 = 0.f;
                if (col0 < NB)
                    v0 = RATIO * (fast_exp(acc1[i][j][2*rp]   - sub[i][rp]) + EPSF);
                if (col0 + 1 < NB)
                    v1 = RATIO * (fast_exp(acc1[i][j][2*rp+1] - sub[i][rp]) + EPSF);
                Qs[row*QSTR + (col0 >> 1)] = packh2(v0, v1);
            }
    {
        const unsigned* cb = (const unsigned*)(g_ctxT + (size_t)bh*CTXW*MPAD);
        #pragma unroll
        for (int i = tid; i < 3200; i += 256) {
            int r = i / 40, c4 = (i % 40) * 4;
            uint4 v = *(const uint4*)(cb + r*160 + c4);
            *(uint4*)&Ct[r*QSTR + c4] = v;
        }
    }
    __syncthreads();

    const int wm2 = warp >> 1, wn2 = warp & 1;
    float acc2[5][4];
    #pragma unroll
    for (int j = 0; j < 5; j++)
        #pragma unroll
        for (int r = 0; r < 4; r++) acc2[j][r] = 0.f;

    #pragma unroll 5
    for (int s = 0; s < 20; s++) {
        const int base = s*8;
        unsigned af[4], bf[5][2];
        const unsigned* ap = Qs + (wm2*16 + qg)*QSTR + base + qt;
        af[0] = ap[0];
        af[1] = ap[8*QSTR];
        af[2] = ap[4];
        af[3] = ap[8*QSTR + 4];
        #pragma unroll
        for (int j = 0; j < 5; j++) {
            const unsigned* bp = Ct + (wn2*40 + j*8 + qg)*QSTR + base + qt;
            bf[j][0] = bp[0];
            bf[j][1] = bp[4];
        }
        #pragma unroll
        for (int j = 0; j < 5; j++)
            mma_f16(acc2[j], af, bf[j]);
    }

    #pragma unroll
    for (int j = 0; j < 5; j++)
        #pragma unroll
        for (int r = 0; r < 4; r++) {
            int col = wn2*40 + j*8 + qt*2 + (r & 1);
            if (col == 64) {
                int row = wm2*16 + qg + 8*(r >> 1);
                s_dnm[row] = acc2[j][r];
            }
        }
    __syncthreads();

    float invd0 = 1.0f / s_dnm[wm2*16 + qg];
    float invd1 = 1.0f / s_dnm[wm2*16 + qg + 8];
    __half* ob = g_o + ((size_t)b*SEQ + n0)*DIM + hh*DH;
    #pragma unroll
    for (int j = 0; j < 5; j++)
        #pragma unroll
        for (int r = 0; r < 4; r++) {
            int col = wn2*40 + j*8 + qt*2 + (r & 1);
            if (col < 64) {
                int row = wm2*16 + qg + 8*(r >> 1);
                ob[(size_t)row*DIM + col] = __float2half_rn(acc2[j][r] * ((r >> 1) ? invd1 : invd0));
            }
        }
}

// ---------------- ctx: read raw xp (fp32 kpT), fuse exp->half, fp16 MMA vs vT ----------------
__global__ void __launch_bounds__(256) ctx_kernel()
{
    __shared__ unsigned Xs[64*HSTR];
    __shared__ unsigned Bs[80*HSTR];
    const int tid = threadIdx.x, lane = tid & 31, warp = tid >> 5;
    const int qg = lane >> 2, qt = lane & 3;
    const int wm = warp >> 1, wn = warp & 1;
    const int f0 = blockIdx.x * 64, bh = blockIdx.y;
    const int nbase = blockIdx.z * (SEQ / SPLITK);
    const float km = g_kmax;

    if (tid >= 64 && tid < 80) {
        unsigned val = (tid == 64) ? 0x3C003C00u : 0u;
        #pragma unroll
        for (int c = 0; c < 32; c++) Bs[tid*HSTR + c] = val;
    }

    float acc[5][4];
    #pragma unroll
    for (int j = 0; j < 5; j++)
        #pragma unroll
        for (int r = 0; r < 4; r++) acc[j][r] = 0.f;

    for (int ch = 0; ch < SEQ/SPLITK; ch += 64) {
        __syncthreads();
        const int n0 = nbase + ch;
        #pragma unroll
        for (int i = tid; i < 64*16; i += 256) {
            int f = i >> 4, c = (i & 15);
            float4 v  = *(const float4*)(g_kpT + ((size_t)bh*MPAD + f0 + f)*SEQ + n0 + c*4);
            float4 dg = *(const float4*)(g_diag + (size_t)bh*SEQ + n0 + c*4);
            float e0 = RATIO * (fast_exp(v.x - dg.x - km) + EPSF);
            float e1 = RATIO * (fast_exp(v.y - dg.y - km) + EPSF);
            float e2 = RATIO * (fast_exp(v.z - dg.z - km) + EPSF);
            float e3 = RATIO * (fast_exp(v.w - dg.w - km) + EPSF);
            Xs[f*HSTR + 2*c]   = packh2(e0, e1);
            Xs[f*HSTR + 2*c+1] = packh2(e2, e3);
        }
        #pragma unroll
        for (int i = tid; i < 512; i += 256) {
            int d = i >> 3, c4 = (i & 7) * 4;
            const unsigned* vp = (const unsigned*)(g_vT + ((size_t)bh*DH + d)*SEQ + n0);
            *(uint4*)&Bs[d*HSTR + c4] = *(const uint4*)(vp + c4);
        }
        __syncthreads();
        #pragma unroll
        for (int s = 0; s < 4; s++) {
            const int base = s*8;
            unsigned af[4], bf[5][2];
            const unsigned* ap = Xs + (wm*16 + qg)*HSTR + base + qt;
            af[0] = ap[0];
            af[1] = ap[8*HSTR];
            af[2] = ap[4];
            af[3] = ap[8*HSTR + 4];
            #pragma unroll
            for (int j = 0; j < 5; j++) {
                const unsigned* bp = Bs + (wn*40 + j*8 + qg)*HSTR + base + qt;
                bf[j][0] = bp[0];
                bf[j][1] = bp[4];
            }
            #pragma unroll
            for (int j = 0; j < 5; j++)
                mma_f16(acc[j], af, bf[j]);
        }
    }

    float* cb = g_ctx + (size_t)bh*MPAD*CTXW;
    #pragma unroll
    for (int j = 0; j < 5; j++)
        #pragma unroll
        for (int r = 0; r < 4; r++) {
            int row = wm*16 + qg + 8*(r >> 1);
            int col = wn*40 + j*8 + qt*2 + (r & 1);
            if (col < 65)
                atomicAdd(&cb[(f0 + row)*CTXW + col], acc[j][r]);
        }
}

// ---------------- final fc ----------------
__global__ void __launch_bounds__(256) fc_kernel(
    const float* __restrict__ x, const float* __restrict__ w,
    const float* __restrict__ bias, float* __restrict__ out)
{
    __shared__ float xs[8*DIM];
    int tid = threadIdx.x;
    int m0 = blockIdx.x * 8;
    for (int i = tid; i < 8*DIM/4; i += 256)
        ((float4*)xs)[i] = ((const float4*)(x + (size_t)m0*DIM))[i];
    __syncthreads();
    int r = tid >> 5, c = tid & 31;
    float acc = 0.f;
    const float* xr = &xs[r*DIM];
    #pragma unroll 8
    for (int k = 0; k < DIM; k++) acc += xr[k] * w[k*OUTD + c];
    out[(size_t)(m0 + r)*OUTD + c] = acc + bias[c];
}

// ---------------- host launcher ----------------
extern "C" void kernel_launch(void* const* d_in, const int* in_sizes, int n_in,
                              void* d_out, int out_size)
{
    (void)in_sizes; (void)n_in; (void)out_size;
    const float* src  = (const float*)d_in[0];
    const float* proj = (const float*)d_in[1];
    const float* ln1g = (const float*)d_in[2];
    const float* ln1b = (const float*)d_in[3];
    const float* Wq   = (const float*)d_in[4];
    const float* Wk   = (const float*)d_in[5];
    const float* Wv   = (const float*)d_in[6];
    const float* Wo   = (const float*)d_in[7];
    const float* bo   = (const float*)d_in[8];
    const float* ln2g = (const float*)d_in[9];
    const float* ln2b = (const float*)d_in[10];
    const float* W1   = (const float*)d_in[11];
    const float* b1   = (const float*)d_in[12];
    const float* W2   = (const float*)d_in[13];
    const float* b2   = (const float*)d_in[14];
    const float* fcw  = (const float*)d_in[15];
    const float* fcb  = (const float*)d_in[16];
    float* out = (float*)d_out;

    float *xp;
    __half *hp, *qkvb, *ob, *ffb, *wh, *pH;
    cudaGetSymbolAddress((void**)&xp,   g_x);
    cudaGetSymbolAddress((void**)&hp,   g_h);
    cudaGetSymbolAddress((void**)&qkvb, g_qkv);
    cudaGetSymbolAddress((void**)&ob,   g_o);
    cudaGetSymbolAddress((void**)&ffb,  g_ff);
    cudaGetSymbolAddress((void**)&wh,   g_wh);
    cudaGetSymbolAddress((void**)&pH,   g_projH);

    const int gemm_smem = STG*2*(128*20)*4;   // 81920
    cudaFuncSetAttribute(hgemm_kernel<0,0,0,1,1>, cudaFuncAttributeMaxDynamicSharedMemorySize, gemm_smem);
    cudaFuncSetAttribute(hgemm_kernel<1,1,0,0,0>, cudaFuncAttributeMaxDynamicSharedMemorySize, gemm_smem);
    cudaFuncSetAttribute(hgemm_kernel<1,0,1,1,0>, cudaFuncAttributeMaxDynamicSharedMemorySize, gemm_smem);
    cudaFuncSetAttribute(xfeat_kernel<0>, cudaFuncAttributeMaxDynamicSharedMemorySize, XF_SMEM);
    cudaFuncSetAttribute(xfeat_kernel<1>, cudaFuncAttributeMaxDynamicSharedMemorySize, XF_SMEM);

    copy_src_kernel<<<(MROWS*DIM + 255)/256, 256>>>(src);

    dim3 tb(32, 8);
    trh_kernel<<<dim3(DIM/32, DIM/32, DEPTH), tb>>>(Wq, wh + WQKVOFF,                    DIM, DIM, (size_t)QKVN*DIM);
    trh_kernel<<<dim3(DIM/32, DIM/32, DEPTH), tb>>>(Wk, wh + WQKVOFF + (size_t)512*DIM,  DIM, DIM, (size_t)QKVN*DIM);
    trh_kernel<<<dim3(DIM/32, DIM/32, DEPTH), tb>>>(Wv, wh + WQKVOFF + (size_t)1024*DIM, DIM, DIM, (size_t)QKVN*DIM);
    trh_kernel<<<dim3(DIM/32, DIM/32, DEPTH), tb>>>(Wo, wh + WOOFF, DIM, DIM, (size_t)DIM*DIM);
    trh_kernel<<<dim3(FFD/32, DIM/32, DEPTH), tb>>>(W1, wh + W1OFF, DIM, FFD, (size_t)DIM*FFD);
    trh_kernel<<<dim3(DIM/32, FFD/32, DEPTH), tb>>>(W2, wh + W2OFF, FFD, DIM, (size_t)FFD*DIM);
    projh_kernel<<<(DEPTH*MPAD*DH + 255)/256, 256>>>(proj);

    dim3 gq(QKVN/128, MROWS/128);   // 12 x 256
    dim3 gg(DIM/128, MROWS/128);    // 4 x 256
    dim3 gf(FFD/128, MROWS/128);    // 16 x 256
    dim3 xg(SEQ/64, BH);            // 128 x 32

    for (int L = 0; L < DEPTH; L++) {
        const __half* pL = pH + (size_t)L*MPAD*DH;
        ln_kernel<<<MROWS, 128>>>(xp, ln1g + L*DIM, ln1b + L*DIM, hp);
        hgemm_kernel<0,0,0,1,1><<<gq, 128, gemm_smem>>>(hp, wh + WQKVOFF + (size_t)L*QKVN*DIM, 0, 0, qkvb, MROWS, QKVN, DIM);
        reset_kernel<<<(BH*MPAD*CTXW + 255)/256, 256>>>();
        xfeat_kernel<0><<<xg, 256, XF_SMEM>>>(pL, qkvb + DIM);        // k cols [512,1024)
        ctx_kernel<<<dim3(MPAD/64, BH, SPLITK), 256>>>();
        ctxt_kernel<<<(BH*CTXW*MPAD + 255)/256, 256>>>();
        xfeat_kernel<1><<<xg, 256, XF_SMEM>>>(pL, qkvb);              // q cols [0,512)
        hgemm_kernel<1,1,0,0,0><<<gg, 128, gemm_smem>>>(ob, wh + WOOFF + (size_t)L*DIM*DIM, bo + L*DIM, xp, xp, MROWS, DIM, DIM);
        ln_kernel<<<MROWS, 128>>>(xp, ln2g + L*DIM, ln2b + L*DIM, hp);
        hgemm_kernel<1,0,1,1,0><<<gf, 128, gemm_smem>>>(hp, wh + W1OFF + (size_t)L*FFD*DIM, b1 + L*FFD, 0, ffb, MROWS, FFD, DIM);
        hgemm_kernel<1,1,0,0,0><<<gg, 128, gemm_smem>>>(ffb, wh + W2OFF + (size_t)L*DIM*FFD, b2 + L*DIM, xp, xp, MROWS, DIM, FFD);
    }
    fc_kernel<<<MROWS/8, 256>>>(xp, fcw, fcb, out);
}

// round 16
// speedup vs baseline: 1.0519x; 1.0307x over previous
#include <cuda_runtime.h>
#include <cuda_fp16.h>
#include <math.h>
#include <stdint.h>

#define DEPTH  6
#define DIM    512
#define QKVN   1536
#define HEADS  8
#define DH     64
#define NB     266
#define FFD    2048
#define OUTD   32
#define BATCH  4
#define SEQ    8192
#define MROWS  (BATCH*SEQ)   // 32768
#define BH     (BATCH*HEADS) // 32
#define MPAD   320
#define CTXW   80
#define BSTR   332           // fp32 stage stride (xfeat0)
#define HSTR   36            // uint stride for [*][64-half] tiles
#define QSTR   164           // uint stride for [*][320-half] tiles
#define EPSF   1e-4f
#define DN     0.3535533905932738f
#define RATIO  0.06131393394849658f
#define SPLITK 4
#define STG    4

// fp16 weight scratch offsets (halfs) — TRANSPOSED [N][K] layout, QKV concatenated
#define WQKVOFF 0
#define WOOFF   (3*DEPTH*DIM*DIM)
#define W1OFF   (4*DEPTH*DIM*DIM)
#define W2OFF   (4*DEPTH*DIM*DIM + DEPTH*DIM*FFD)
#define WRTOT   (4*DEPTH*DIM*DIM + 2*DEPTH*DIM*FFD)

// xfeat smem layout (uints): region0 23616 overlapped, aux after
#define AUXOFF  23616
#define XF_SMEM ((AUXOFF + 392)*4)

// ---------------- scratch ----------------
__device__ __align__(256) float  g_x[MROWS*DIM];
__device__ __align__(256) __half g_h[MROWS*DIM];
__device__ __align__(256) __half g_qkv[(size_t)MROWS*QKVN];
__device__ __align__(256) __half g_o[MROWS*DIM];
__device__ __align__(256) __half g_ff[(size_t)MROWS*FFD];
__device__ __align__(256) __half g_kpT[(size_t)BH*MPAD*SEQ];   // xp - diag, half
__device__ __align__(256) float  g_ctx[BH*MPAD*CTXW];
__device__ __align__(256) __half g_ctxT[BH*CTXW*MPAD];
__device__ __align__(256) __half g_vT[(size_t)BH*DH*SEQ];
__device__ __align__(256) __half g_projH[DEPTH*MPAD*DH];
__device__ __align__(256) __half g_wh[WRTOT];
__device__ float g_kmax;

// ---------------- helpers ----------------
__device__ __forceinline__ void atomicMaxF(float* addr, float val) {
    int old = __float_as_int(*addr);
    while (__int_as_float(old) < val) {
        int assumed = old;
        old = atomicCAS((int*)addr, assumed, __float_as_int(val));
        if (old == assumed) break;
    }
}

__device__ __forceinline__ float fast_exp(float x) {
    float t = x * 1.4426950408889634f;
    t = fminf(fmaxf(t, -126.0f), 126.0f);
    float z = t + 12582912.0f;
    int n = __float_as_int(z) - 0x4B400000;
    float f = t - (z - 12582912.0f);
    float p = 1.33335581e-3f;
    p = fmaf(p, f, 9.61812911e-3f);
    p = fmaf(p, f, 5.55041087e-2f);
    p = fmaf(p, f, 2.40226507e-1f);
    p = fmaf(p, f, 6.93147181e-1f);
    p = fmaf(p, f, 1.0f);
    return p * __int_as_float((n + 127) << 23);
}

__device__ __forceinline__ float fast_rcp(float x) {
    float y = __int_as_float(0x7EF311C3 - __float_as_int(x));
    y = y * (2.0f - x * y);
    y = y * (2.0f - x * y);
    y = y * (2.0f - x * y);
    return y;
}

__device__ __forceinline__ float gelu_fast(float x) {
    float u = 0.7978845608028654f * (x + 0.044715f * x * x * x);
    u = fminf(fmaxf(u, -9.0f), 9.0f);
    float E = fast_exp(2.0f * u);
    float th = 1.0f - 2.0f * fast_rcp(E + 1.0f);
    return 0.5f * x * (1.0f + th);
}

__device__ __forceinline__ unsigned packh2(float a, float b) {
    __half2 h = __floats2half2_rn(a, b);
    return *(unsigned*)&h;
}

__device__ __forceinline__ void mma_f16(float (&d)[4], const unsigned (&a)[4], const unsigned (&b)[2]) {
    asm volatile(
        "mma.sync.aligned.m16n8k16.row.col.f32.f16.f16.f32 "
        "{%0,%1,%2,%3}, {%4,%5,%6,%7}, {%8,%9}, {%0,%1,%2,%3};\n"
        : "+f"(d[0]), "+f"(d[1]), "+f"(d[2]), "+f"(d[3])
        : "r"(a[0]), "r"(a[1]), "r"(a[2]), "r"(a[3]), "r"(b[0]), "r"(b[1]));
}

__device__ __forceinline__ void ldsm4(unsigned &d0, unsigned &d1, unsigned &d2, unsigned &d3,
                                      const unsigned* p) {
    unsigned a = (unsigned)__cvta_generic_to_shared(p);
    asm volatile("ldmatrix.sync.aligned.m8n8.x4.shared.b16 {%0,%1,%2,%3}, [%4];"
                 : "=r"(d0), "=r"(d1), "=r"(d2), "=r"(d3) : "r"(a));
}

__device__ __forceinline__ void cp16(void* s, const void* g) {
    unsigned saddr = (unsigned)__cvta_generic_to_shared(s);
    asm volatile("cp.async.cg.shared.global [%0], [%1], 16;\n" :: "r"(saddr), "l"(g));
}
__device__ __forceinline__ void cp_commit() { asm volatile("cp.async.commit_group;\n"); }
template<int N> __device__ __forceinline__ void cp_wait() {
    asm volatile("cp.async.wait_group %0;\n" :: "n"(N));
}

// ---------------- init / reset / prep ----------------
__global__ void copy_src_kernel(const float* __restrict__ src) {
    int i = blockIdx.x * blockDim.x + threadIdx.x;
    if (i < MROWS*DIM) g_x[i] = src[i];
}

__global__ void reset_kernel() {
    int i = blockIdx.x * blockDim.x + threadIdx.x;
    if (i < BH*MPAD*CTXW) g_ctx[i] = 0.f;
    if (i == 0) g_kmax = __int_as_float(0xff800000);
}

// transpose + fp16 weights: src [L][K][N] fp32 -> dst rows [n][K] half
__global__ void trh_kernel(const float* __restrict__ src, __half* __restrict__ dst,
                           int K, int N, size_t dstLayerStride) {
    __shared__ float t[32][33];
    const float* s = src + (size_t)blockIdx.z*K*N;
    __half* d = dst + (size_t)blockIdx.z*dstLayerStride;
    int gn = blockIdx.x*32, gk = blockIdx.y*32;
    int tx = threadIdx.x, ty = threadIdx.y;
    #pragma unroll
    for (int i = 0; i < 32; i += 8)
        t[ty+i][tx] = s[(size_t)(gk+ty+i)*N + gn+tx];
    __syncthreads();
    #pragma unroll
    for (int i = 0; i < 32; i += 8)
        d[(size_t)(gn+ty+i)*K + gk+tx] = __float2half_rn(t[tx][ty+i]);
}

// all layers' proj as half [L][MPAD][DH] (natural layout, zero-padded)
__global__ void projh_kernel(const float* __restrict__ proj) {
    int i = blockIdx.x * blockDim.x + threadIdx.x;
    if (i < DEPTH*MPAD*DH) {
        int L = i / (MPAD*DH);
        int r = i - L*(MPAD*DH);
        int f = r / DH, d = r - f*DH;
        float v = (f < NB) ? proj[((size_t)L*NB + f)*DH + d] : 0.f;
        g_projH[i] = __float2half_rn(v);
    }
}

// per-layer: g_ctx [bh][m][80] fp32 -> g_ctxT [bh][col][m] half
__global__ void ctxt_kernel() {
    int i = blockIdx.x * blockDim.x + threadIdx.x;
    if (i < BH*CTXW*MPAD) {
        int bh = i / (CTXW*MPAD);
        int r = i - bh*(CTXW*MPAD);
        int col = r / MPAD, m = r - col*MPAD;
        g_ctxT[i] = __float2half_rn(g_ctx[((size_t)bh*MPAD + m)*CTXW + col]);
    }
}

// ---------------- LayerNorm (fp16 output) ----------------
__global__ void __launch_bounds__(128) ln_kernel(
    const float* __restrict__ x, const float* __restrict__ g,
    const float* __restrict__ b, __half* __restrict__ o)
{
    int row = blockIdx.x, tid = threadIdx.x, lane = tid & 31, w = tid >> 5;
    const float4 xv = ((const float4*)(x + (size_t)row*DIM))[tid];
    float s = xv.x + xv.y + xv.z + xv.w;
    float q = xv.x*xv.x + xv.y*xv.y + xv.z*xv.z + xv.w*xv.w;
    #pragma unroll
    for (int off = 16; off; off >>= 1) {
        s += __shfl_xor_sync(0xffffffffu, s, off);
        q += __shfl_xor_sync(0xffffffffu, q, off);
    }
    __shared__ float ss[4], sq[4];
    if (lane == 0) { ss[w] = s; sq[w] = q; }
    __syncthreads();
    float S = ss[0]+ss[1]+ss[2]+ss[3];
    float Q = sq[0]+sq[1]+sq[2]+sq[3];
    float mean = S * (1.0f/DIM);
    float var  = Q * (1.0f/DIM) - mean*mean;
    float inv  = rsqrtf(var + 1e-5f);
    float4 gv = ((const float4*)g)[tid];
    float4 bv = ((const float4*)b)[tid];
    __half2 h0 = __floats2half2_rn((xv.x - mean)*inv*gv.x + bv.x,
                                   (xv.y - mean)*inv*gv.y + bv.y);
    __half2 h1 = __floats2half2_rn((xv.z - mean)*inv*gv.z + bv.z,
                                   (xv.w - mean)*inv*gv.w + bv.w);
    __half2* op = (__half2*)(o + (size_t)row*DIM) + tid*2;
    op[0] = h0;
    op[1] = h1;
}

// ---------------- FP16 GEMM, cp.async 4-stage + ldmatrix (128 thr, warp 64x64, BK=32) ----
// QKVF: v-region columns (col0>=1024) are written transposed to g_vT instead of C.
template<int BIASF, int RESF, int GELUF, int OUTHALF, int QKVF>
__global__ void __launch_bounds__(128, 2) hgemm_kernel(
    const __half* __restrict__ A, const __half* __restrict__ WT,
    const float* __restrict__ bias, const float* __restrict__ res,
    void* __restrict__ Cv, int M, int N, int K)
{
    extern __shared__ unsigned smu[];
    const int TSZ = 128*20;
    unsigned* As = smu;
    unsigned* Bs = smu + STG*TSZ;

    const int tid = threadIdx.x, lane = tid & 31, warp = tid >> 5;
    const int wm = warp >> 1, wn = warp & 1;
    const int qg = lane >> 2, qt = lane & 3;
    const __half* Ab = A  + (size_t)(blockIdx.y*128)*K;
    const __half* Wb = WT + (size_t)(blockIdx.x*128)*K;

    const int cr = tid >> 2, cs = tid & 3;
    int so[4];
    const __half *ga[4], *gb[4];
    #pragma unroll
    for (int g = 0; g < 4; g++) {
        so[g] = (cr + 32*g)*20 + cs*4;
        ga[g] = Ab + (size_t)(cr + 32*g)*K + cs*8;
        gb[g] = Wb + (size_t)(cr + 32*g)*K + cs*8;
    }

    const int aidx = (wm*64 + (lane & 7) + ((lane >> 3) & 1)*8)*20 + ((lane >> 4) << 2);
    const int bidx = (wn*64 + (lane & 7) + ((lane >> 4) & 1)*8)*20 + (((lane >> 3) & 1) << 2);

    float acc[4][8][4];
    #pragma unroll
    for (int i = 0; i < 4; i++)
        #pragma unroll
        for (int j = 0; j < 8; j++)
            #pragma unroll
            for (int r = 0; r < 4; r++) acc[i][j][r] = 0.f;

    const int ntiles = K >> 5;

    #pragma unroll
    for (int s = 0; s < STG-1; s++) {
        unsigned* Ad = As + s*TSZ;
        unsigned* Bd = Bs + s*TSZ;
        const int ko = s*32;
        #pragma unroll
        for (int g = 0; g < 4; g++) {
            cp16(Ad + so[g], ga[g] + ko);
            cp16(Bd + so[g], gb[g] + ko);
        }
        cp_commit();
    }
    cp_wait<STG-2>();
    __syncthreads();

    #pragma unroll 1
    for (int kt = 0; kt < ntiles; kt++) {
        const int stg = kt & (STG-1);
        if (kt + STG-1 < ntiles) {
            const int ns = (kt + STG-1) & (STG-1);
            unsigned* Ad = As + ns*TSZ;
            unsigned* Bd = Bs + ns*TSZ;
            const int ko = (kt + STG-1) * 32;
            #pragma unroll
            for (int g = 0; g < 4; g++) {
                cp16(Ad + so[g], ga[g] + ko);
                cp16(Bd + so[g], gb[g] + ko);
            }
        }
        cp_commit();

        const unsigned* At = As + stg*TSZ;
        const unsigned* Bt = Bs + stg*TSZ;
        #pragma unroll
        for (int kk = 0; kk < 2; kk++) {
            unsigned af[4][4], bf[8][2];
            #pragma unroll
            for (int i = 0; i < 4; i++)
                ldsm4(af[i][0], af[i][1], af[i][2], af[i][3],
                      At + aidx + i*320 + kk*8);
            #pragma unroll
            for (int j2 = 0; j2 < 4; j2++)
                ldsm4(bf[2*j2][0], bf[2*j2][1], bf[2*j2+1][0], bf[2*j2+1][1],
                      Bt + bidx + j2*320 + kk*8);
            #pragma unroll
            for (int i = 0; i < 4; i++)
                #pragma unroll
                for (int j = 0; j < 8; j++)
                    mma_f16(acc[i][j], af[i], bf[j]);
        }
        cp_wait<STG-2>();
        __syncthreads();
    }

    const int row0 = blockIdx.y*128 + wm*64;
    const int col0 = blockIdx.x*128 + wn*64;
    float*  Cf = (float*)Cv;
    __half* Ch = (__half*)Cv;

    if (QKVF && col0 >= 1024) {
        #pragma unroll
        for (int i = 0; i < 4; i++) {
            #pragma unroll
            for (int j = 0; j < 8; j++) {
                int r = row0 + i*16 + qg;
                int c = col0 + j*8 + qt*2;
                int b = r >> 13, n = r & (SEQ-1);
                int bh = b*8 + ((c - 1024) >> 6);
                int d  = (c - 1024) & 63;
                __half* vp = g_vT + ((size_t)bh*DH + d)*SEQ;
                vp[n]            = __float2half_rn(acc[i][j][0]);
                vp[SEQ + n]      = __float2half_rn(acc[i][j][1]);
                vp[n + 8]        = __float2half_rn(acc[i][j][2]);
                vp[SEQ + n + 8]  = __float2half_rn(acc[i][j][3]);
            }
        }
        return;
    }

    #pragma unroll
    for (int i = 0; i < 4; i++) {
        #pragma unroll
        for (int j = 0; j < 8; j++) {
            int r = row0 + i*16 + qg;
            int c = col0 + j*8 + qt*2;
            float b0 = 0.f, b1 = 0.f;
            if (BIASF) { b0 = bias[c]; b1 = bias[c+1]; }
            float v0 = acc[i][j][0] + b0;
            float v1 = acc[i][j][1] + b1;
            float v2 = acc[i][j][2] + b0;
            float v3 = acc[i][j][3] + b1;
            if (GELUF) { v0 = gelu_fast(v0); v1 = gelu_fast(v1); v2 = gelu_fast(v2); v3 = gelu_fast(v3); }
            if (RESF) {
                const float2 r0v = *(const float2*)(res + (size_t)r*N + c);
                const float2 r1v = *(const float2*)(res + (size_t)(r+8)*N + c);
                v0 += r0v.x; v1 += r0v.y; v2 += r1v.x; v3 += r1v.y;
            }
            if (OUTHALF) {
                *(__half2*)(Ch + (size_t)r*N + c)     = __floats2half2_rn(v0, v1);
                *(__half2*)(Ch + (size_t)(r+8)*N + c) = __floats2half2_rn(v2, v3);
            } else {
                *(float2*)(Cf + (size_t)r*N + c)     = make_float2(v0, v1);
                *(float2*)(Cf + (size_t)(r+8)*N + c) = make_float2(v2, v3);
            }
        }
    }
}

// ---------------- feature-map kernels (FP16 MMA) ----------------
// ISQ=0: k path — (xp - diag) -> g_kpT half (masked=-30), blockmax(xp) -> g_kmax
// ISQ=1: q path — xq MMA + rowmax + exp -> qp -> MMA with ctxT -> g_o
template<int ISQ>
__global__ void __launch_bounds__(256) xfeat_kernel(const __half* __restrict__ pH,
                                                   const __half* __restrict__ srcb)
{
    extern __shared__ unsigned smu[];
    unsigned* As = smu;
    unsigned* Ph = smu + 64*HSTR;
    float*    fstage = (float*)smu;
    unsigned* Qs = smu;
    unsigned* Ct = smu + 64*QSTR;
    float* s_aux  = (float*)(smu + AUXOFF);
    float* s_diag = s_aux;
    float* s_rmax = s_diag + 64;
    float* s_dnm  = s_rmax + 256;
    float* s_wm   = s_dnm + 64;

    const int tid = threadIdx.x, lane = tid & 31, warp = tid >> 5;
    const int qg = lane >> 2, qt = lane & 3;
    const int wm = warp >> 2, wn = warp & 3;
    const int bh = blockIdx.y, b = bh >> 3, hh = bh & 7;
    const int n0 = blockIdx.x * 64;
    const __half* src = srcb + ((size_t)b*SEQ + n0)*QKVN + hh*DH;
    const __half2 dn2 = __float2half2_rn(DN);

    #pragma unroll
    for (int i = tid; i < 64*8; i += 256) {
        int r = i >> 3, c4 = (i & 7) * 4;
        uint4 v = *(const uint4*)((const unsigned*)(src + (size_t)r*QKVN) + c4);
        __half2* hv = (__half2*)&v;
        hv[0] = __hmul2(hv[0], dn2);
        hv[1] = __hmul2(hv[1], dn2);
        hv[2] = __hmul2(hv[2], dn2);
        hv[3] = __hmul2(hv[3], dn2);
        *(uint4*)&As[r*HSTR + c4] = v;
    }
    #pragma unroll
    for (int i = tid; i < 2560; i += 256) {
        int r = i >> 3, c4 = (i & 7) * 4;
        uint4 v = *(const uint4*)((const unsigned*)pH + r*32 + c4);
        *(uint4*)&Ph[r*HSTR + c4] = v;
    }
    __syncthreads();

    if (tid < 64) {
        float s = 0.f;
        #pragma unroll 8
        for (int d = 0; d < 32; d++) {
            __half2 h = *(__half2*)&As[tid*HSTR + d];
            float2 f = __half22float2(h);
            s += f.x*f.x + f.y*f.y;
        }
        s_diag[tid] = 0.5f * s;
    }
    __syncthreads();

    float acc1[2][10][4];
    #pragma unroll
    for (int i = 0; i < 2; i++)
        #pragma unroll
        for (int j = 0; j < 10; j++)
            #pragma unroll
            for (int r = 0; r < 4; r++) acc1[i][j][r] = 0.f;

    #pragma unroll
    for (int s = 0; s < 4; s++) {
        const int base = s*8;
        unsigned af[2][4], bf[10][2];
        #pragma unroll
        for (int i = 0; i < 2; i++) {
            const unsigned* ap = As + (wm*32 + i*16 + qg)*HSTR + base + qt;
            af[i][0] = ap[0];
            af[i][1] = ap[8*HSTR];
            af[i][2] = ap[4];
            af[i][3] = ap[8*HSTR + 4];
        }
        #pragma unroll
        for (int j = 0; j < 10; j++) {
            const unsigned* bp = Ph + (wn*80 + j*8 + qg)*HSTR + base + qt;
            bf[j][0] = bp[0];
            bf[j][1] = bp[4];
        }
        #pragma unroll
        for (int i = 0; i < 2; i++)
            #pragma unroll
            for (int j = 0; j < 10; j++)
                mma_f16(acc1[i][j], af[i], bf[j]);
    }

    if (!ISQ) {
        float m = __int_as_float(0xff800000);
        #pragma unroll
        for (int i = 0; i < 2; i++)
            #pragma unroll
            for (int j = 0; j < 10; j++)
                #pragma unroll
                for (int r = 0; r < 4; r++) {
                    int col = wn*80 + j*8 + qt*2 + (r & 1);
                    if (col < NB) m = fmaxf(m, acc1[i][j][r]);
                }
        #pragma unroll
        for (int off = 16; off; off >>= 1) m = fmaxf(m, __shfl_xor_sync(0xffffffffu, m, off));
        if (lane == 0) s_wm[warp] = m;
        __syncthreads();
        if (tid == 0) {
            float mm = s_wm[0];
            #pragma unroll
            for (int i = 1; i < 8; i++) mm = fmaxf(mm, s_wm[i]);
            atomicMaxF(&g_kmax, mm);
        }
        // stage y = xp - diag (fp32), masked cols -> -30
        #pragma unroll
        for (int i = 0; i < 2; i++)
            #pragma unroll
            for (int j = 0; j < 10; j++)
                #pragma unroll
                for (int r = 0; r < 4; r++) {
                    int row = wm*32 + i*16 + qg + 8*(r >> 1);
                    int col = wn*80 + j*8 + qt*2 + (r & 1);
                    fstage[row*BSTR + col] = (col < NB) ? (acc1[i][j][r] - s_diag[row]) : -30.f;
                }
        __syncthreads();
        // transposed half store to g_kpT[bh][f][n]
        #pragma unroll
        for (int i = tid; i < 64*80; i += 256) {
            int n = i & 63, f4 = (i >> 6) * 4;
            float4 v = *(const float4*)&fstage[n*BSTR + f4];
            __half* dst = g_kpT + ((size_t)bh*MPAD + f4)*SEQ + n0 + n;
            dst[0]      = __float2half_rn(v.x);
            dst[SEQ]    = __float2half_rn(v.y);
            dst[2*SEQ]  = __float2half_rn(v.z);
            dst[3*SEQ]  = __float2half_rn(v.w);
        }
        return;
    }

    // rowmax
    #pragma unroll
    for (int i = 0; i < 2; i++) {
        #pragma unroll
        for (int h = 0; h < 2; h++) {
            float m = __int_as_float(0xff800000);
            #pragma unroll
            for (int j = 0; j < 10; j++) {
                #pragma unroll
                for (int rb = 0; rb < 2; rb++) {
                    int col = wn*80 + j*8 + qt*2 + rb;
                    if (col < NB) m = fmaxf(m, acc1[i][j][2*h + rb]);
                }
            }
            m = fmaxf(m, __shfl_xor_sync(0xffffffffu, m, 1));
            m = fmaxf(m, __shfl_xor_sync(0xffffffffu, m, 2));
            if (qt == 0) s_rmax[(wm*32 + i*16 + qg + 8*h)*4 + wn] = m;
        }
    }
    __syncthreads();

    float sub[2][2];
    #pragma unroll
    for (int i = 0; i < 2; i++)
        #pragma unroll
        for (int h = 0; h < 2; h++) {
            int row = wm*32 + i*16 + qg + 8*h;
            float m = fmaxf(fmaxf(s_rmax[row*4+0], s_rmax[row*4+1]),
                            fmaxf(s_rmax[row*4+2], s_rmax[row*4+3]));
            sub[i][h] = m + s_diag[row];
        }
    #pragma unroll
    for (int i = 0; i < 2; i++)
        #pragma unroll
        for (int j = 0; j < 10; j++)
            #pragma unroll
            for (int rp = 0; rp < 2; rp++) {
                int row = wm*32 + i*16 + qg + 8*rp;
                int col0 = wn*80 + j*8 + qt*2;
                float v0 = 0.f, v1 = 0.f;
                if (col0 < NB)
                    v0 = RATIO * (fast_exp(acc1[i][j][2*rp]   - sub[i][rp]) + EPSF);
                if (col0 + 1 < NB)
                    v1 = RATIO * (fast_exp(acc1[i][j][2*rp+1] - sub[i][rp]) + EPSF);
                Qs[row*QSTR + (col0 >> 1)] = packh2(v0, v1);
            }
    {
        const unsigned* cb = (const unsigned*)(g_ctxT + (size_t)bh*CTXW*MPAD);
        #pragma unroll
        for (int i = tid; i < 3200; i += 256) {
            int r = i / 40, c4 = (i % 40) * 4;
            uint4 v = *(const uint4*)(cb + r*160 + c4);
            *(uint4*)&Ct[r*QSTR + c4] = v;
        }
    }
    __syncthreads();

    const int wm2 = warp >> 1, wn2 = warp & 1;
    float acc2[5][4];
    #pragma unroll
    for (int j = 0; j < 5; j++)
        #pragma unroll
        for (int r = 0; r < 4; r++) acc2[j][r] = 0.f;

    #pragma unroll 5
    for (int s = 0; s < 20; s++) {
        const int base = s*8;
        unsigned af[4], bf[5][2];
        const unsigned* ap = Qs + (wm2*16 + qg)*QSTR + base + qt;
        af[0] = ap[0];
        af[1] = ap[8*QSTR];
        af[2] = ap[4];
        af[3] = ap[8*QSTR + 4];
        #pragma unroll
        for (int j = 0; j < 5; j++) {
            const unsigned* bp = Ct + (wn2*40 + j*8 + qg)*QSTR + base + qt;
            bf[j][0] = bp[0];
            bf[j][1] = bp[4];
        }
        #pragma unroll
        for (int j = 0; j < 5; j++)
            mma_f16(acc2[j], af, bf[j]);
    }

    #pragma unroll
    for (int j = 0; j < 5; j++)
        #pragma unroll
        for (int r = 0; r < 4; r++) {
            int col = wn2*40 + j*8 + qt*2 + (r & 1);
            if (col == 64) {
                int row = wm2*16 + qg + 8*(r >> 1);
                s_dnm[row] = acc2[j][r];
            }
        }
    __syncthreads();

    float invd0 = 1.0f / s_dnm[wm2*16 + qg];
    float invd1 = 1.0f / s_dnm[wm2*16 + qg + 8];
    __half* ob = g_o + ((size_t)b*SEQ + n0)*DIM + hh*DH;
    #pragma unroll
    for (int j = 0; j < 5; j++)
        #pragma unroll
        for (int r = 0; r < 4; r++) {
            int col = wn2*40 + j*8 + qt*2 + (r & 1);
            if (col < 64) {
                int row = wm2*16 + qg + 8*(r >> 1);
                ob[(size_t)row*DIM + col] = __float2half_rn(acc2[j][r] * ((r >> 1) ? invd1 : invd0));
            }
        }
}

// ---------------- ctx: read y=xp-diag (half kpT), exp->half, fp16 MMA vs vT ----------------
__global__ void __launch_bounds__(256) ctx_kernel()
{
    __shared__ unsigned Xs[64*HSTR];
    __shared__ unsigned Bs[80*HSTR];
    const int tid = threadIdx.x, lane = tid & 31, warp = tid >> 5;
    const int qg = lane >> 2, qt = lane & 3;
    const int wm = warp >> 1, wn = warp & 1;
    const int f0 = blockIdx.x * 64, bh = blockIdx.y;
    const int nbase = blockIdx.z * (SEQ / SPLITK);
    const float km = g_kmax;

    if (tid >= 64 && tid < 80) {
        unsigned val = (tid == 64) ? 0x3C003C00u : 0u;
        #pragma unroll
        for (int c = 0; c < 32; c++) Bs[tid*HSTR + c] = val;
    }

    float acc[5][4];
    #pragma unroll
    for (int j = 0; j < 5; j++)
        #pragma unroll
        for (int r = 0; r < 4; r++) acc[j][r] = 0.f;

    for (int ch = 0; ch < SEQ/SPLITK; ch += 64) {
        __syncthreads();
        const int n0 = nbase + ch;
        #pragma unroll
        for (int i = tid; i < 512; i += 256) {
            int f = i >> 3, c8 = (i & 7) * 8;
            uint4 v = *(const uint4*)(g_kpT + ((size_t)bh*MPAD + f0 + f)*SEQ + n0 + c8);
            __half2* hv = (__half2*)&v;
            uint4 o;
            unsigned* ou = (unsigned*)&o;
            #pragma unroll
            for (int t = 0; t < 4; t++) {
                float2 f2 = __half22float2(hv[t]);
                ou[t] = packh2(RATIO * (fast_exp(f2.x - km) + EPSF),
                               RATIO * (fast_exp(f2.y - km) + EPSF));
            }
            *(uint4*)&Xs[f*HSTR + (c8 >> 1)] = o;
        }
        #pragma unroll
        for (int i = tid; i < 512; i += 256) {
            int d = i >> 3, c4 = (i & 7) * 4;
            const unsigned* vp = (const unsigned*)(g_vT + ((size_t)bh*DH + d)*SEQ + n0);
            *(uint4*)&Bs[d*HSTR + c4] = *(const uint4*)(vp + c4);
        }
        __syncthreads();
        #pragma unroll
        for (int s = 0; s < 4; s++) {
            const int base = s*8;
            unsigned af[4], bf[5][2];
            const unsigned* ap = Xs + (wm*16 + qg)*HSTR + base + qt;
            af[0] = ap[0];
            af[1] = ap[8*HSTR];
            af[2] = ap[4];
            af[3] = ap[8*HSTR + 4];
            #pragma unroll
            for (int j = 0; j < 5; j++) {
                const unsigned* bp = Bs + (wn*40 + j*8 + qg)*HSTR + base + qt;
                bf[j][0] = bp[0];
                bf[j][1] = bp[4];
            }
            #pragma unroll
            for (int j = 0; j < 5; j++)
                mma_f16(acc[j], af, bf[j]);
        }
    }

    float* cb = g_ctx + (size_t)bh*MPAD*CTXW;
    #pragma unroll
    for (int j = 0; j < 5; j++)
        #pragma unroll
        for (int r = 0; r < 4; r++) {
            int row = wm*16 + qg + 8*(r >> 1);
            int col = wn*40 + j*8 + qt*2 + (r & 1);
            if (col < 65)
                atomicAdd(&cb[(f0 + row)*CTXW + col], acc[j][r]);
        }
}

// ---------------- final fc ----------------
__global__ void __launch_bounds__(256) fc_kernel(
    const float* __restrict__ x, const float* __restrict__ w,
    const float* __restrict__ bias, float* __restrict__ out)
{
    __shared__ float xs[8*DIM];
    int tid = threadIdx.x;
    int m0 = blockIdx.x * 8;
    for (int i = tid; i < 8*DIM/4; i += 256)
        ((float4*)xs)[i] = ((const float4*)(x + (size_t)m0*DIM))[i];
    __syncthreads();
    int r = tid >> 5, c = tid & 31;
    float acc = 0.f;
    const float* xr = &xs[r*DIM];
    #pragma unroll 8
    for (int k = 0; k < DIM; k++) acc += xr[k] * w[k*OUTD + c];
    out[(size_t)(m0 + r)*OUTD + c] = acc + bias[c];
}

// ---------------- host launcher ----------------
extern "C" void kernel_launch(void* const* d_in, const int* in_sizes, int n_in,
                              void* d_out, int out_size)
{
    (void)in_sizes; (void)n_in; (void)out_size;
    const float* src  = (const float*)d_in[0];
    const float* proj = (const float*)d_in[1];
    const float* ln1g = (const float*)d_in[2];
    const float* ln1b = (const float*)d_in[3];
    const float* Wq   = (const float*)d_in[4];
    const float* Wk   = (const float*)d_in[5];
    const float* Wv   = (const float*)d_in[6];
    const float* Wo   = (const float*)d_in[7];
    const float* bo   = (const float*)d_in[8];
    const float* ln2g = (const float*)d_in[9];
    const float* ln2b = (const float*)d_in[10];
    const float* W1   = (const float*)d_in[11];
    const float* b1   = (const float*)d_in[12];
    const float* W2   = (const float*)d_in[13];
    const float* b2   = (const float*)d_in[14];
    const float* fcw  = (const float*)d_in[15];
    const float* fcb  = (const float*)d_in[16];
    float* out = (float*)d_out;

    float *xp;
    __half *hp, *qkvb, *ob, *ffb, *wh, *pH;
    cudaGetSymbolAddress((void**)&xp,   g_x);
    cudaGetSymbolAddress((void**)&hp,   g_h);
    cudaGetSymbolAddress((void**)&qkvb, g_qkv);
    cudaGetSymbolAddress((void**)&ob,   g_o);
    cudaGetSymbolAddress((void**)&ffb,  g_ff);
    cudaGetSymbolAddress((void**)&wh,   g_wh);
    cudaGetSymbolAddress((void**)&pH,   g_projH);

    const int gemm_smem = STG*2*(128*20)*4;   // 81920
    cudaFuncSetAttribute(hgemm_kernel<0,0,0,1,1>, cudaFuncAttributeMaxDynamicSharedMemorySize, gemm_smem);
    cudaFuncSetAttribute(hgemm_kernel<1,1,0,0,0>, cudaFuncAttributeMaxDynamicSharedMemorySize, gemm_smem);
    cudaFuncSetAttribute(hgemm_kernel<1,0,1,1,0>, cudaFuncAttributeMaxDynamicSharedMemorySize, gemm_smem);
    cudaFuncSetAttribute(xfeat_kernel<0>, cudaFuncAttributeMaxDynamicSharedMemorySize, XF_SMEM);
    cudaFuncSetAttribute(xfeat_kernel<1>, cudaFuncAttributeMaxDynamicSharedMemorySize, XF_SMEM);

    copy_src_kernel<<<(MROWS*DIM + 255)/256, 256>>>(src);

    dim3 tb(32, 8);
    trh_kernel<<<dim3(DIM/32, DIM/32, DEPTH), tb>>>(Wq, wh + WQKVOFF,                    DIM, DIM, (size_t)QKVN*DIM);
    trh_kernel<<<dim3(DIM/32, DIM/32, DEPTH), tb>>>(Wk, wh + WQKVOFF + (size_t)512*DIM,  DIM, DIM, (size_t)QKVN*DIM);
    trh_kernel<<<dim3(DIM/32, DIM/32, DEPTH), tb>>>(Wv, wh + WQKVOFF + (size_t)1024*DIM, DIM, DIM, (size_t)QKVN*DIM);
    trh_kernel<<<dim3(DIM/32, DIM/32, DEPTH), tb>>>(Wo, wh + WOOFF, DIM, DIM, (size_t)DIM*DIM);
    trh_kernel<<<dim3(FFD/32, DIM/32, DEPTH), tb>>>(W1, wh + W1OFF, DIM, FFD, (size_t)DIM*FFD);
    trh_kernel<<<dim3(DIM/32, FFD/32, DEPTH), tb>>>(W2, wh + W2OFF, FFD, DIM, (size_t)FFD*DIM);
    projh_kernel<<<(DEPTH*MPAD*DH + 255)/256, 256>>>(proj);

    dim3 gq(QKVN/128, MROWS/128);   // 12 x 256
    dim3 gg(DIM/128, MROWS/128);    // 4 x 256
    dim3 gf(FFD/128, MROWS/128);    // 16 x 256
    dim3 xg(SEQ/64, BH);            // 128 x 32

    for (int L = 0; L < DEPTH; L++) {
        const __half* pL = pH + (size_t)L*MPAD*DH;
        ln_kernel<<<MROWS, 128>>>(xp, ln1g + L*DIM, ln1b + L*DIM, hp);
        hgemm_kernel<0,0,0,1,1><<<gq, 128, gemm_smem>>>(hp, wh + WQKVOFF + (size_t)L*QKVN*DIM, 0, 0, qkvb, MROWS, QKVN, DIM);
        reset_kernel<<<(BH*MPAD*CTXW + 255)/256, 256>>>();
        xfeat_kernel<0><<<xg, 256, XF_SMEM>>>(pL, qkvb + DIM);        // k cols [512,1024)
        ctx_kernel<<<dim3(MPAD/64, BH, SPLITK), 256>>>();
        ctxt_kernel<<<(BH*CTXW*MPAD + 255)/256, 256>>>();
        xfeat_kernel<1><<<xg, 256, XF_SMEM>>>(pL, qkvb);              // q cols [0,512)
        hgemm_kernel<1,1,0,0,0><<<gg, 128, gemm_smem>>>(ob, wh + WOOFF + (size_t)L*DIM*DIM, bo + L*DIM, xp, xp, MROWS, DIM, DIM);
        ln_kernel<<<MROWS, 128>>>(xp, ln2g + L*DIM, ln2b + L*DIM, hp);
        hgemm_kernel<1,0,1,1,0><<<gf, 128, gemm_smem>>>(hp, wh + W1OFF + (size_t)L*FFD*DIM, b1 + L*FFD, 0, ffb, MROWS, FFD, DIM);
        hgemm_kernel<1,1,0,0,0><<<gg, 128, gemm_smem>>>(ffb, wh + W2OFF + (size_t)L*DIM*FFD, b2 + L*DIM, xp, xp, MROWS, DIM, FFD);
    }
    fc_kernel<<<MROWS/8, 256>>>(xp, fcw, fcb, out);
}